// round 1
// baseline (speedup 1.0000x reference)
#include <cuda_runtime.h>
#include <math.h>

#define NN   50000
#define EE   800000
#define ET   (EE + NN)          // edges + self loops
#define INC  128
#define HC   192                // HEADS*HID = 3*64
#define MIDC 64
#define OUTC 32

// ---------------- scratch (device globals: allocation-free) ----------------
__device__ float g_h1[NN * HC];
__device__ float g_h2[NN * HC];
__device__ float g_hx[NN * HC];
__device__ float g_mid[NN * MIDC];
__device__ float g_as[NN * 3];
__device__ float g_ad[NN * 3];
__device__ int   g_deg[NN];
__device__ int   g_ctr[NN];
__device__ int   g_rowptr[NN + 1];
__device__ int   g_srcs[ET];

// ---------------- helpers ----------------
__device__ __forceinline__ float lrelu(float v) { return v > 0.f ? v : 0.2f * v; }
__device__ __forceinline__ float elu_f(float v) { return v > 0.f ? v : expm1f(v); }
__device__ __forceinline__ float wmax(float v) {
    #pragma unroll
    for (int o = 16; o > 0; o >>= 1) v = fmaxf(v, __shfl_xor_sync(0xffffffffu, v, o));
    return v;
}
__device__ __forceinline__ float wsum(float v) {
    #pragma unroll
    for (int o = 16; o > 0; o >>= 1) v += __shfl_xor_sync(0xffffffffu, v, o);
    return v;
}

// ---------------- CSR build ----------------
__global__ void zero_kernel() {
    int i = blockIdx.x * blockDim.x + threadIdx.x;
    if (i < NN) { g_deg[i] = 0; g_ctr[i] = 0; }
}

__global__ void count_kernel(const int* __restrict__ dst) {
    int i = blockIdx.x * blockDim.x + threadIdx.x;
    if (i >= ET) return;
    int d = (i < EE) ? dst[i] : (i - EE);
    atomicAdd(&g_deg[d], 1);
}

// single-block exclusive scan over g_deg -> g_rowptr  (1024 threads)
__global__ void scan_kernel() {
    __shared__ int part[1024];
    const int per = (NN + 1023) / 1024;
    int t = threadIdx.x;
    int start = t * per;
    int end = min(start + per, NN);
    int s = 0;
    for (int i = start; i < end; i++) s += g_deg[i];
    part[t] = s;
    __syncthreads();
    for (int off = 1; off < 1024; off <<= 1) {
        int v = (t >= off) ? part[t - off] : 0;
        __syncthreads();
        part[t] += v;
        __syncthreads();
    }
    int run = part[t] - s;   // exclusive prefix
    for (int i = start; i < end; i++) { g_rowptr[i] = run; run += g_deg[i]; }
    if (t == 1023) g_rowptr[NN] = part[1023];
}

__global__ void bucket_kernel(const int* __restrict__ src, const int* __restrict__ dst) {
    int i = blockIdx.x * blockDim.x + threadIdx.x;
    if (i >= ET) return;
    int s, d;
    if (i < EE) { s = src[i]; d = dst[i]; } else { s = i - EE; d = s; }
    int pos = atomicAdd(&g_ctr[d], 1);
    g_srcs[g_rowptr[d] + pos] = s;
}

// ---------------- GEMM: C[M,Nc] = A[M,K] @ B[K,Nc] (+bias) ----------------
// 64x64 tile, 256 threads, 4x4 microtile. K must be a multiple of 16 (128/192/64/64: yes)
__global__ void gemm_kernel(const float* __restrict__ A, const float* __restrict__ B,
                            const float* __restrict__ bias, float* __restrict__ C,
                            int M, int K, int Nc) {
    __shared__ float As[16][64];
    __shared__ float Bs[16][64];
    int tid = threadIdx.x;
    int tx = tid & 15, ty = tid >> 4;
    int row0 = blockIdx.y * 64, col0 = blockIdx.x * 64;
    float acc[4][4] = {};
    for (int kt = 0; kt < K; kt += 16) {
        #pragma unroll
        for (int i = tid; i < 1024; i += 256) {
            int m = i >> 4, k = i & 15;
            int r = row0 + m;
            As[k][m] = (r < M) ? A[(size_t)r * K + kt + k] : 0.f;
        }
        #pragma unroll
        for (int i = tid; i < 1024; i += 256) {
            int k = i >> 6, n = i & 63;
            int c = col0 + n;
            Bs[k][n] = (c < Nc) ? B[(size_t)(kt + k) * Nc + c] : 0.f;
        }
        __syncthreads();
        #pragma unroll
        for (int k = 0; k < 16; k++) {
            float a[4], b[4];
            #pragma unroll
            for (int i = 0; i < 4; i++) a[i] = As[k][ty * 4 + i];
            #pragma unroll
            for (int j = 0; j < 4; j++) b[j] = Bs[k][tx * 4 + j];
            #pragma unroll
            for (int i = 0; i < 4; i++)
                #pragma unroll
                for (int j = 0; j < 4; j++) acc[i][j] += a[i] * b[j];
        }
        __syncthreads();
    }
    #pragma unroll
    for (int i = 0; i < 4; i++) {
        int r = row0 + ty * 4 + i;
        if (r >= M) continue;
        #pragma unroll
        for (int j = 0; j < 4; j++) {
            int c = col0 + tx * 4 + j;
            if (c < Nc) C[(size_t)r * Nc + c] = acc[i][j] + (bias ? bias[c] : 0.f);
        }
    }
}

// ---------------- per-node attention projections (warp per node) ----------------
__global__ void alpha_kernel(const float* __restrict__ h, const float* __restrict__ asrc,
                             const float* __restrict__ adst) {
    int gw = (blockIdx.x * blockDim.x + threadIdx.x) >> 5;
    int lane = threadIdx.x & 31;
    if (gw >= NN) return;
    const float* hp = h + (size_t)gw * HC;
    float s[3], d[3];
    #pragma unroll
    for (int hh = 0; hh < 3; hh++) {
        int c0 = hh * 64 + lane, c1 = c0 + 32;
        float v0 = hp[c0], v1 = hp[c1];
        s[hh] = wsum(v0 * asrc[c0] + v1 * asrc[c1]);
        d[hh] = wsum(v0 * adst[c0] + v1 * adst[c1]);
    }
    if (lane == 0) {
        g_as[gw * 3 + 0] = s[0]; g_as[gw * 3 + 1] = s[1]; g_as[gw * 3 + 2] = s[2];
        g_ad[gw * 3 + 0] = d[0]; g_ad[gw * 3 + 1] = d[1]; g_ad[gw * 3 + 2] = d[2];
    }
}

// ---------------- GAT aggregation: warp per destination node, no atomics ----------------
// out[n,:] = elu( sum_e softmax(lrelu(as[src]+ad[n])) * h[src,:] + bias )
__global__ void agg_kernel(const float* __restrict__ h, const float* __restrict__ bias,
                           float* __restrict__ out) {
    int gw = (blockIdx.x * blockDim.x + threadIdx.x) >> 5;
    int lane = threadIdx.x & 31;
    if (gw >= NN) return;
    int beg = g_rowptr[gw], end = g_rowptr[gw + 1];
    float ad0 = g_ad[gw * 3 + 0], ad1 = g_ad[gw * 3 + 1], ad2 = g_ad[gw * 3 + 2];

    // pass 1: per-head max
    float m0 = -1e30f, m1 = -1e30f, m2 = -1e30f;
    for (int i = beg + lane; i < end; i += 32) {
        int s = g_srcs[i];
        m0 = fmaxf(m0, lrelu(g_as[s * 3 + 0] + ad0));
        m1 = fmaxf(m1, lrelu(g_as[s * 3 + 1] + ad1));
        m2 = fmaxf(m2, lrelu(g_as[s * 3 + 2] + ad2));
    }
    m0 = wmax(m0); m1 = wmax(m1); m2 = wmax(m2);

    // pass 2: denominators
    float d0 = 0.f, d1 = 0.f, d2 = 0.f;
    for (int i = beg + lane; i < end; i += 32) {
        int s = g_srcs[i];
        d0 += __expf(lrelu(g_as[s * 3 + 0] + ad0) - m0);
        d1 += __expf(lrelu(g_as[s * 3 + 1] + ad1) - m1);
        d2 += __expf(lrelu(g_as[s * 3 + 2] + ad2) - m2);
    }
    d0 = wsum(d0); d1 = wsum(d1); d2 = wsum(d2);
    float i0 = 1.f / (d0 + 1e-16f), i1 = 1.f / (d1 + 1e-16f), i2 = 1.f / (d2 + 1e-16f);

    // pass 3: weighted gather-accumulate (coalesced 192-float rows, 6 regs/lane)
    float a0c0 = 0.f, a0c1 = 0.f, a1c0 = 0.f, a1c1 = 0.f, a2c0 = 0.f, a2c1 = 0.f;
    for (int i = beg; i < end; i++) {
        int s = g_srcs[i];                       // broadcast load
        float w0 = __expf(lrelu(g_as[s * 3 + 0] + ad0) - m0) * i0;
        float w1 = __expf(lrelu(g_as[s * 3 + 1] + ad1) - m1) * i1;
        float w2 = __expf(lrelu(g_as[s * 3 + 2] + ad2) - m2) * i2;
        const float* hs = h + (size_t)s * HC;
        a0c0 += hs[lane +   0] * w0;
        a0c1 += hs[lane +  32] * w0;
        a1c0 += hs[lane +  64] * w1;
        a1c1 += hs[lane +  96] * w1;
        a2c0 += hs[lane + 128] * w2;
        a2c1 += hs[lane + 160] * w2;
    }
    float* op = out + (size_t)gw * HC;
    op[lane +   0] = elu_f(a0c0 + bias[lane +   0]);
    op[lane +  32] = elu_f(a0c1 + bias[lane +  32]);
    op[lane +  64] = elu_f(a1c0 + bias[lane +  64]);
    op[lane +  96] = elu_f(a1c1 + bias[lane +  96]);
    op[lane + 128] = elu_f(a2c0 + bias[lane + 128]);
    op[lane + 160] = elu_f(a2c1 + bias[lane + 160]);
}

// ---------------- launch ----------------
extern "C" void kernel_launch(void* const* d_in, const int* in_sizes, int n_in,
                              void* d_out, int out_size) {
    const float* x     = (const float*)d_in[0];
    const int*   ei    = (const int*)  d_in[1];
    const float* W1    = (const float*)d_in[2];
    const float* asrc1 = (const float*)d_in[3];
    const float* adst1 = (const float*)d_in[4];
    const float* b1    = (const float*)d_in[5];
    const float* W2    = (const float*)d_in[6];
    const float* asrc2 = (const float*)d_in[7];
    const float* adst2 = (const float*)d_in[8];
    const float* b2    = (const float*)d_in[9];
    const float* Wf1   = (const float*)d_in[10];
    const float* bf1   = (const float*)d_in[11];
    const float* Wf2   = (const float*)d_in[12];
    const float* bf2   = (const float*)d_in[13];
    float* out = (float*)d_out;

    float *h1, *h2, *hx, *mid;
    cudaGetSymbolAddress((void**)&h1,  g_h1);
    cudaGetSymbolAddress((void**)&h2,  g_h2);
    cudaGetSymbolAddress((void**)&hx,  g_hx);
    cudaGetSymbolAddress((void**)&mid, g_mid);

    const int* srcp = ei;
    const int* dstp = ei + EE;

    // CSR build (shared between both layers)
    zero_kernel<<<(NN + 255) / 256, 256>>>();
    count_kernel<<<(ET + 255) / 256, 256>>>(dstp);
    scan_kernel<<<1, 1024>>>();
    bucket_kernel<<<(ET + 255) / 256, 256>>>(srcp, dstp);

    dim3 gThreads(256);
    int warpBlocks = (NN * 32 + 255) / 256;

    // layer 1
    gemm_kernel<<<dim3((HC + 63) / 64, (NN + 63) / 64), gThreads>>>(x, W1, nullptr, h1, NN, INC, HC);
    alpha_kernel<<<warpBlocks, 256>>>(h1, asrc1, adst1);
    agg_kernel<<<warpBlocks, 256>>>(h1, b1, hx);

    // layer 2
    gemm_kernel<<<dim3((HC + 63) / 64, (NN + 63) / 64), gThreads>>>(hx, W2, nullptr, h2, NN, HC, HC);
    alpha_kernel<<<warpBlocks, 256>>>(h2, asrc2, adst2);
    agg_kernel<<<warpBlocks, 256>>>(h2, b2, hx);

    // MLP head
    gemm_kernel<<<dim3((MIDC + 63) / 64, (NN + 63) / 64), gThreads>>>(hx, Wf1, bf1, mid, NN, HC, MIDC);
    gemm_kernel<<<dim3((OUTC + 63) / 64, (NN + 63) / 64), gThreads>>>(mid, Wf2, bf2, out, NN, MIDC, OUTC);
}

// round 2
// speedup vs baseline: 1.6306x; 1.6306x over previous
#include <cuda_runtime.h>
#include <math.h>
#include <stdint.h>

#define NN   50000
#define EE   800000
#define ET   (EE + NN)          // edges + self loops
#define INC  128
#define HC   192                // HEADS*HID = 3*64
#define MIDC 64
#define OUTC 32

// ---------------- scratch (device globals: allocation-free) ----------------
__device__ float g_h1[NN * HC];
__device__ float g_h2[NN * HC];
__device__ float g_hx[NN * HC];
__device__ float g_mid[NN * MIDC];
__device__ float g_as[NN * 3];
__device__ float g_ad[NN * 3];
__device__ int   g_deg[NN];
__device__ int   g_ctr[NN];
__device__ int   g_rowptr[NN + 1];
__device__ int   g_srcs[ET];

// ---------------- helpers ----------------
__device__ __forceinline__ float lrelu(float v) { return v > 0.f ? v : 0.2f * v; }
__device__ __forceinline__ float elu_f(float v) { return v > 0.f ? v : expm1f(v); }
__device__ __forceinline__ float wmax(float v) {
    #pragma unroll
    for (int o = 16; o > 0; o >>= 1) v = fmaxf(v, __shfl_xor_sync(0xffffffffu, v, o));
    return v;
}
__device__ __forceinline__ float wsum(float v) {
    #pragma unroll
    for (int o = 16; o > 0; o >>= 1) v += __shfl_xor_sync(0xffffffffu, v, o);
    return v;
}
__device__ __forceinline__ void split_tf32(float v, uint32_t &hi, uint32_t &lo) {
    uint32_t h; asm("cvt.rna.tf32.f32 %0, %1;" : "=r"(h) : "f"(v));
    float r = v - __uint_as_float(h);
    uint32_t l; asm("cvt.rna.tf32.f32 %0, %1;" : "=r"(l) : "f"(r));
    hi = h; lo = l;
}
__device__ __forceinline__ void mma_tf32(float* c, const uint32_t* a, const uint32_t* b) {
    asm volatile(
        "mma.sync.aligned.m16n8k8.row.col.f32.tf32.tf32.f32 "
        "{%0,%1,%2,%3}, {%4,%5,%6,%7}, {%8,%9}, {%0,%1,%2,%3};"
        : "+f"(c[0]), "+f"(c[1]), "+f"(c[2]), "+f"(c[3])
        : "r"(a[0]), "r"(a[1]), "r"(a[2]), "r"(a[3]), "r"(b[0]), "r"(b[1]));
}

// ---------------- CSR build ----------------
__global__ void zero_kernel() {
    int i = blockIdx.x * blockDim.x + threadIdx.x;
    if (i < NN) { g_deg[i] = 0; g_ctr[i] = 0; }
}

__global__ void count_kernel(const int* __restrict__ dst) {
    int i = blockIdx.x * blockDim.x + threadIdx.x;
    if (i >= ET) return;
    int d = (i < EE) ? dst[i] : (i - EE);
    atomicAdd(&g_deg[d], 1);
}

__global__ void scan_kernel() {
    __shared__ int part[1024];
    const int per = (NN + 1023) / 1024;
    int t = threadIdx.x;
    int start = t * per;
    int end = min(start + per, NN);
    int s = 0;
    for (int i = start; i < end; i++) s += g_deg[i];
    part[t] = s;
    __syncthreads();
    for (int off = 1; off < 1024; off <<= 1) {
        int v = (t >= off) ? part[t - off] : 0;
        __syncthreads();
        part[t] += v;
        __syncthreads();
    }
    int run = part[t] - s;
    for (int i = start; i < end; i++) { g_rowptr[i] = run; run += g_deg[i]; }
    if (t == 1023) g_rowptr[NN] = part[1023];
}

__global__ void bucket_kernel(const int* __restrict__ src, const int* __restrict__ dst) {
    int i = blockIdx.x * blockDim.x + threadIdx.x;
    if (i >= ET) return;
    int s, d;
    if (i < EE) { s = src[i]; d = dst[i]; } else { s = i - EE; d = s; }
    int pos = atomicAdd(&g_ctr[d], 1);
    g_srcs[g_rowptr[d] + pos] = s;
}

// ---------------- 3xTF32 tensor-core GEMM ----------------
// C[M,Nc] = A[M,K] @ B[K,Nc] (+bias). Tile 128x64x32, 256 threads (8 warps: 4M x 2N).
// K must be a multiple of 32 (128/192/64/64: yes).
#define BM 128
#define BN 64
#define BKK 32
#define ASTR 36   // bank pattern 4r+k -> conflict-free A fragment loads
#define BSTR 72   // bank pattern 8k+n -> conflict-free B fragment loads
#define SM_FLOATS (2*BM*ASTR + 2*BKK*BSTR)   // 13824 floats = 55296 B

__global__ void __launch_bounds__(256) gemm_tc(const float* __restrict__ A,
                                               const float* __restrict__ B,
                                               const float* __restrict__ bias,
                                               float* __restrict__ C,
                                               int M, int K, int Nc) {
    extern __shared__ float smem[];
    float* Abig = smem;
    float* Asml = Abig + BM * ASTR;
    float* Bbig = Asml + BM * ASTR;
    float* Bsml = Bbig + BKK * BSTR;

    int tid = threadIdx.x;
    int lane = tid & 31, warp = tid >> 5;
    int wm = warp & 3, wn = warp >> 2;           // warp tile: rows wm*32.., cols wn*32..
    int row0 = blockIdx.y * BM, col0 = blockIdx.x * BN;
    int lq = lane >> 2, lr = lane & 3;           // quad row / lane-in-quad

    float acc[2][4][4];
    #pragma unroll
    for (int i = 0; i < 2; i++)
        #pragma unroll
        for (int j = 0; j < 4; j++)
            #pragma unroll
            for (int k = 0; k < 4; k++) acc[i][j][k] = 0.f;

    int ar = tid >> 3;        // 0..31
    int ac4 = (tid & 7) * 4;  // k offset of float4

    for (int kt = 0; kt < K; kt += BKK) {
        // load A tile 128x32 (float4, guarded rows), split into tf32 hi/lo
        #pragma unroll
        for (int p = 0; p < 4; p++) {
            int m = p * 32 + ar;
            int gr = row0 + m;
            float4 v = make_float4(0.f, 0.f, 0.f, 0.f);
            if (gr < M) v = *(const float4*)(A + (size_t)gr * K + kt + ac4);
            uint32_t h, l;
            split_tf32(v.x, h, l); Abig[m*ASTR + ac4+0] = __uint_as_float(h); Asml[m*ASTR + ac4+0] = __uint_as_float(l);
            split_tf32(v.y, h, l); Abig[m*ASTR + ac4+1] = __uint_as_float(h); Asml[m*ASTR + ac4+1] = __uint_as_float(l);
            split_tf32(v.z, h, l); Abig[m*ASTR + ac4+2] = __uint_as_float(h); Asml[m*ASTR + ac4+2] = __uint_as_float(l);
            split_tf32(v.w, h, l); Abig[m*ASTR + ac4+3] = __uint_as_float(h); Asml[m*ASTR + ac4+3] = __uint_as_float(l);
        }
        // load B tile 32x64 (scalar, guarded cols)
        #pragma unroll
        for (int i = tid; i < BKK * BN; i += 256) {
            int k = i >> 6, n = i & 63;
            int gc = col0 + n;
            float v = (gc < Nc) ? B[(size_t)(kt + k) * Nc + gc] : 0.f;
            uint32_t h, l;
            split_tf32(v, h, l);
            Bbig[k*BSTR + n] = __uint_as_float(h);
            Bsml[k*BSTR + n] = __uint_as_float(l);
        }
        __syncthreads();

        const uint32_t* Abu = (const uint32_t*)Abig;
        const uint32_t* Alu = (const uint32_t*)Asml;
        const uint32_t* Bbu = (const uint32_t*)Bbig;
        const uint32_t* Blu = (const uint32_t*)Bsml;

        #pragma unroll
        for (int ks = 0; ks < 4; ks++) {
            int k0 = ks * 8;
            uint32_t ab[2][4], al[2][4], bb[4][2], bl[4][2];
            #pragma unroll
            for (int mi = 0; mi < 2; mi++) {
                int r = wm * 32 + mi * 16;
                int i00 = (r + lq) * ASTR + k0 + lr;
                int i10 = (r + 8 + lq) * ASTR + k0 + lr;
                ab[mi][0] = Abu[i00];     ab[mi][1] = Abu[i10];
                ab[mi][2] = Abu[i00 + 4]; ab[mi][3] = Abu[i10 + 4];
                al[mi][0] = Alu[i00];     al[mi][1] = Alu[i10];
                al[mi][2] = Alu[i00 + 4]; al[mi][3] = Alu[i10 + 4];
            }
            #pragma unroll
            for (int ni = 0; ni < 4; ni++) {
                int c = wn * 32 + ni * 8;
                int j0 = (k0 + lr) * BSTR + c + lq;
                int j1 = (k0 + 4 + lr) * BSTR + c + lq;
                bb[ni][0] = Bbu[j0]; bb[ni][1] = Bbu[j1];
                bl[ni][0] = Blu[j0]; bl[ni][1] = Blu[j1];
            }
            #pragma unroll
            for (int mi = 0; mi < 2; mi++)
                #pragma unroll
                for (int ni = 0; ni < 4; ni++) {
                    mma_tf32(acc[mi][ni], ab[mi], bb[ni]);   // hi*hi
                    mma_tf32(acc[mi][ni], ab[mi], bl[ni]);   // hi*lo
                    mma_tf32(acc[mi][ni], al[mi], bb[ni]);   // lo*hi
                }
        }
        __syncthreads();
    }

    // epilogue
    #pragma unroll
    for (int mi = 0; mi < 2; mi++) {
        int r0 = row0 + wm * 32 + mi * 16 + lq;
        #pragma unroll
        for (int ni = 0; ni < 4; ni++) {
            int c = col0 + wn * 32 + ni * 8 + lr * 2;
            if (r0 < M) {
                if (c < Nc)     C[(size_t)r0 * Nc + c]     = acc[mi][ni][0] + (bias ? bias[c]     : 0.f);
                if (c + 1 < Nc) C[(size_t)r0 * Nc + c + 1] = acc[mi][ni][1] + (bias ? bias[c + 1] : 0.f);
            }
            if (r0 + 8 < M) {
                if (c < Nc)     C[(size_t)(r0 + 8) * Nc + c]     = acc[mi][ni][2] + (bias ? bias[c]     : 0.f);
                if (c + 1 < Nc) C[(size_t)(r0 + 8) * Nc + c + 1] = acc[mi][ni][3] + (bias ? bias[c + 1] : 0.f);
            }
        }
    }
}

// ---------------- per-node attention projections (warp per node) ----------------
__global__ void alpha_kernel(const float* __restrict__ h, const float* __restrict__ asrc,
                             const float* __restrict__ adst) {
    int gw = (blockIdx.x * blockDim.x + threadIdx.x) >> 5;
    int lane = threadIdx.x & 31;
    if (gw >= NN) return;
    const float* hp = h + (size_t)gw * HC;
    float s[3], d[3];
    #pragma unroll
    for (int hh = 0; hh < 3; hh++) {
        int c0 = hh * 64 + lane, c1 = c0 + 32;
        float v0 = hp[c0], v1 = hp[c1];
        s[hh] = wsum(v0 * asrc[c0] + v1 * asrc[c1]);
        d[hh] = wsum(v0 * adst[c0] + v1 * adst[c1]);
    }
    if (lane == 0) {
        g_as[gw * 3 + 0] = s[0]; g_as[gw * 3 + 1] = s[1]; g_as[gw * 3 + 2] = s[2];
        g_ad[gw * 3 + 0] = d[0]; g_ad[gw * 3 + 1] = d[1]; g_ad[gw * 3 + 2] = d[2];
    }
}

// ---------------- GAT aggregation: warp per destination node, no atomics ----------------
__global__ void agg_kernel(const float* __restrict__ h, const float* __restrict__ bias,
                           float* __restrict__ out) {
    int gw = (blockIdx.x * blockDim.x + threadIdx.x) >> 5;
    int lane = threadIdx.x & 31;
    if (gw >= NN) return;
    int beg = g_rowptr[gw], end = g_rowptr[gw + 1];
    float ad0 = g_ad[gw * 3 + 0], ad1 = g_ad[gw * 3 + 1], ad2 = g_ad[gw * 3 + 2];

    float m0 = -1e30f, m1 = -1e30f, m2 = -1e30f;
    for (int i = beg + lane; i < end; i += 32) {
        int s = g_srcs[i];
        m0 = fmaxf(m0, lrelu(g_as[s * 3 + 0] + ad0));
        m1 = fmaxf(m1, lrelu(g_as[s * 3 + 1] + ad1));
        m2 = fmaxf(m2, lrelu(g_as[s * 3 + 2] + ad2));
    }
    m0 = wmax(m0); m1 = wmax(m1); m2 = wmax(m2);

    float d0 = 0.f, d1 = 0.f, d2 = 0.f;
    for (int i = beg + lane; i < end; i += 32) {
        int s = g_srcs[i];
        d0 += __expf(lrelu(g_as[s * 3 + 0] + ad0) - m0);
        d1 += __expf(lrelu(g_as[s * 3 + 1] + ad1) - m1);
        d2 += __expf(lrelu(g_as[s * 3 + 2] + ad2) - m2);
    }
    d0 = wsum(d0); d1 = wsum(d1); d2 = wsum(d2);
    float i0 = 1.f / (d0 + 1e-16f), i1 = 1.f / (d1 + 1e-16f), i2 = 1.f / (d2 + 1e-16f);

    float a0c0 = 0.f, a0c1 = 0.f, a1c0 = 0.f, a1c1 = 0.f, a2c0 = 0.f, a2c1 = 0.f;
    for (int i = beg; i < end; i++) {
        int s = g_srcs[i];
        float w0 = __expf(lrelu(g_as[s * 3 + 0] + ad0) - m0) * i0;
        float w1 = __expf(lrelu(g_as[s * 3 + 1] + ad1) - m1) * i1;
        float w2 = __expf(lrelu(g_as[s * 3 + 2] + ad2) - m2) * i2;
        const float* hs = h + (size_t)s * HC;
        a0c0 += hs[lane +   0] * w0;
        a0c1 += hs[lane +  32] * w0;
        a1c0 += hs[lane +  64] * w1;
        a1c1 += hs[lane +  96] * w1;
        a2c0 += hs[lane + 128] * w2;
        a2c1 += hs[lane + 160] * w2;
    }
    float* op = out + (size_t)gw * HC;
    op[lane +   0] = elu_f(a0c0 + bias[lane +   0]);
    op[lane +  32] = elu_f(a0c1 + bias[lane +  32]);
    op[lane +  64] = elu_f(a1c0 + bias[lane +  64]);
    op[lane +  96] = elu_f(a1c1 + bias[lane +  96]);
    op[lane + 128] = elu_f(a2c0 + bias[lane + 128]);
    op[lane + 160] = elu_f(a2c1 + bias[lane + 160]);
}

// ---------------- launch ----------------
extern "C" void kernel_launch(void* const* d_in, const int* in_sizes, int n_in,
                              void* d_out, int out_size) {
    const float* x     = (const float*)d_in[0];
    const int*   ei    = (const int*)  d_in[1];
    const float* W1    = (const float*)d_in[2];
    const float* asrc1 = (const float*)d_in[3];
    const float* adst1 = (const float*)d_in[4];
    const float* b1    = (const float*)d_in[5];
    const float* W2    = (const float*)d_in[6];
    const float* asrc2 = (const float*)d_in[7];
    const float* adst2 = (const float*)d_in[8];
    const float* b2    = (const float*)d_in[9];
    const float* Wf1   = (const float*)d_in[10];
    const float* bf1   = (const float*)d_in[11];
    const float* Wf2   = (const float*)d_in[12];
    const float* bf2   = (const float*)d_in[13];
    float* out = (float*)d_out;

    float *h1, *h2, *hx, *mid;
    cudaGetSymbolAddress((void**)&h1,  g_h1);
    cudaGetSymbolAddress((void**)&h2,  g_h2);
    cudaGetSymbolAddress((void**)&hx,  g_hx);
    cudaGetSymbolAddress((void**)&mid, g_mid);

    const int* srcp = ei;
    const int* dstp = ei + EE;

    const int smemBytes = SM_FLOATS * 4;
    cudaFuncSetAttribute(gemm_tc, cudaFuncAttributeMaxDynamicSharedMemorySize, smemBytes);

    // CSR build (shared between both layers)
    zero_kernel<<<(NN + 255) / 256, 256>>>();
    count_kernel<<<(ET + 255) / 256, 256>>>(dstp);
    scan_kernel<<<1, 1024>>>();
    bucket_kernel<<<(ET + 255) / 256, 256>>>(srcp, dstp);

    int warpBlocks = (NN * 32 + 255) / 256;
    dim3 gdim1((HC + BN - 1) / BN, (NN + BM - 1) / BM);

    // layer 1
    gemm_tc<<<gdim1, 256, smemBytes>>>(x, W1, nullptr, h1, NN, INC, HC);
    alpha_kernel<<<warpBlocks, 256>>>(h1, asrc1, adst1);
    agg_kernel<<<warpBlocks, 256>>>(h1, b1, hx);

    // layer 2
    gemm_tc<<<gdim1, 256, smemBytes>>>(hx, W2, nullptr, h2, NN, HC, HC);
    alpha_kernel<<<warpBlocks, 256>>>(h2, asrc2, adst2);
    agg_kernel<<<warpBlocks, 256>>>(h2, b2, hx);

    // MLP head
    gemm_tc<<<dim3(1, (NN + BM - 1) / BM), 256, smemBytes>>>(hx, Wf1, bf1, mid, NN, HC, MIDC);
    gemm_tc<<<dim3(1, (NN + BM - 1) / BM), 256, smemBytes>>>(mid, Wf2, bf2, out, NN, MIDC, OUTC);
}

// round 4
// speedup vs baseline: 1.8698x; 1.1467x over previous
#include <cuda_runtime.h>
#include <cuda_bf16.h>
#include <math.h>
#include <stdint.h>

#define NN   50000
#define EE   800000
#define ET   (EE + NN)
#define INC  128
#define HC   192
#define OUTC 32

// ---------------- scratch ----------------
__device__ float g_h[NN * HC];
__device__ float g_hx[NN * HC];
__device__ float g_as[NN * 3];
__device__ float g_ad[NN * 3];
__device__ int   g_deg[NN];
__device__ int   g_ctr[NN];
__device__ int   g_rowptr[NN + 1];
__device__ int   g_srcs[ET];
__device__ float g_wf[HC * OUTC];
__device__ float g_bf[OUTC];

// ---------------- helpers ----------------
__device__ __forceinline__ float lrelu(float v) { return v > 0.f ? v : 0.2f * v; }
__device__ __forceinline__ float elu_f(float v) { return v > 0.f ? v : expm1f(v); }
__device__ __forceinline__ float wmax(float v) {
    #pragma unroll
    for (int o = 16; o > 0; o >>= 1) v = fmaxf(v, __shfl_xor_sync(0xffffffffu, v, o));
    return v;
}
__device__ __forceinline__ float wsum(float v) {
    #pragma unroll
    for (int o = 16; o > 0; o >>= 1) v += __shfl_xor_sync(0xffffffffu, v, o);
    return v;
}
__device__ __forceinline__ uint32_t smem_u32(const void* p) {
    uint32_t a;
    asm("{ .reg .u64 t; cvta.to.shared.u64 t, %1; cvt.u32.u64 %0, t; }" : "=r"(a) : "l"(p));
    return a;
}
__device__ __forceinline__ void ldsm4(uint32_t& r0, uint32_t& r1, uint32_t& r2, uint32_t& r3, uint32_t a) {
    asm volatile("ldmatrix.sync.aligned.m8n8.x4.shared.b16 {%0,%1,%2,%3}, [%4];"
                 : "=r"(r0), "=r"(r1), "=r"(r2), "=r"(r3) : "r"(a));
}
__device__ __forceinline__ void mma_bf16(float* c, const uint32_t* a, const uint32_t* b) {
    asm volatile(
        "mma.sync.aligned.m16n8k16.row.col.f32.bf16.bf16.f32 "
        "{%0,%1,%2,%3}, {%4,%5,%6,%7}, {%8,%9}, {%0,%1,%2,%3};"
        : "+f"(c[0]), "+f"(c[1]), "+f"(c[2]), "+f"(c[3])
        : "r"(a[0]), "r"(a[1]), "r"(a[2]), "r"(a[3]), "r"(b[0]), "r"(b[1]));
}
__device__ __forceinline__ uint32_t pack_bf2(float x, float y) {
    __nv_bfloat162 t = __floats2bfloat162_rn(x, y);
    return *(uint32_t*)&t;
}

// ---------------- CSR build ----------------
__global__ void zero_kernel() {
    int i = blockIdx.x * blockDim.x + threadIdx.x;
    if (i < NN) { g_deg[i] = 0; g_ctr[i] = 0; }
}
__global__ void count_kernel(const int* __restrict__ dst) {
    int i = blockIdx.x * blockDim.x + threadIdx.x;
    if (i >= ET) return;
    int d = (i < EE) ? dst[i] : (i - EE);
    atomicAdd(&g_deg[d], 1);
}
__global__ void scan_kernel() {
    __shared__ int part[1024];
    const int per = (NN + 1023) / 1024;
    int t = threadIdx.x;
    int start = t * per, end = min(start + per, NN);
    int s = 0;
    for (int i = start; i < end; i++) s += g_deg[i];
    part[t] = s;
    __syncthreads();
    for (int off = 1; off < 1024; off <<= 1) {
        int v = (t >= off) ? part[t - off] : 0;
        __syncthreads();
        part[t] += v;
        __syncthreads();
    }
    int run = part[t] - s;
    for (int i = start; i < end; i++) { g_rowptr[i] = run; run += g_deg[i]; }
    if (t == 1023) g_rowptr[NN] = part[1023];
}
__global__ void bucket_kernel(const int* __restrict__ src, const int* __restrict__ dst) {
    int i = blockIdx.x * blockDim.x + threadIdx.x;
    if (i >= ET) return;
    int s, d;
    if (i < EE) { s = src[i]; d = dst[i]; } else { s = i - EE; d = s; }
    int pos = atomicAdd(&g_ctr[d], 1);
    g_srcs[g_rowptr[d] + pos] = s;
}

// ---------------- MLP weight fusion: Wf = Wf1@Wf2, bf = bf1@Wf2 + bf2 ----------------
__global__ void fuse_mlp_kernel(const float* __restrict__ Wf1, const float* __restrict__ bf1,
                                const float* __restrict__ Wf2, const float* __restrict__ bf2) {
    int i = blockIdx.x * blockDim.x + threadIdx.x;
    if (i < HC * OUTC) {
        int r = i >> 5, c = i & 31;
        float s = 0.f;
        #pragma unroll 8
        for (int j = 0; j < 64; j++) s += Wf1[r * 64 + j] * Wf2[j * OUTC + c];
        g_wf[i] = s;
    } else if (i < HC * OUTC + OUTC) {
        int c = i - HC * OUTC;
        float s = bf2[c];
        for (int j = 0; j < 64; j++) s += bf1[j] * Wf2[j * OUTC + c];
        g_bf[c] = s;
    }
}

// ---------------- bf16-split tensor-core GEMM ----------------
// C[M,Nc] = A[M,K] @ B[K,Nc] (+bias).
// Tile BM=128 x BN=64, BK=32. 256 threads, 8 warps (4M x 2N), warp tile 32x32.
// smem rows padded to 40 bf16 (80B) -> conflict-free ldmatrix.
#define BM 128
#define BN 64
#define BK 32
#define RS 40   // row stride in bf16 elems (80 bytes, 16B-aligned chunks)

__global__ void __launch_bounds__(256) gemm_bf16(const float* __restrict__ A,
                                                 const float* __restrict__ B,
                                                 const float* __restrict__ bias,
                                                 float* __restrict__ C,
                                                 int M, int K, int Nc) {
    __shared__ __nv_bfloat16 Ahi[BM * RS], Alo[BM * RS];
    __shared__ __nv_bfloat16 Bhi[BN * RS], Blo[BN * RS];

    int tid = threadIdx.x;
    int lane = tid & 31, warp = tid >> 5;
    int wm = warp & 3, wn = warp >> 2;
    int row0 = blockIdx.y * BM, col0 = blockIdx.x * BN;

    uint32_t uAhi = smem_u32(Ahi), uAlo = smem_u32(Alo);
    uint32_t uBhi = smem_u32(Bhi), uBlo = smem_u32(Blo);

    // ldmatrix per-lane address pieces
    int aRow = ((lane & 8) ? 8 : 0) + (lane & 7);   // + chunk via lane>=16
    int aChk = (lane & 16) ? 1 : 0;

    float acc[2][4][4];
    #pragma unroll
    for (int i = 0; i < 2; i++)
        #pragma unroll
        for (int j = 0; j < 4; j++)
            #pragma unroll
            for (int k = 0; k < 4; k++) acc[i][j][k] = 0.f;

    const int ntiles = K / BK;
    for (int t = 0; t < ntiles; t++) {
        int kt = t * BK;
        // ---- load A tile: 128 rows x 32 k, float4 -> bf16 hi/lo ----
        #pragma unroll
        for (int i = tid; i < BM * BK / 4; i += 256) {   // 1024
            int m = i >> 3, k0 = (i & 7) * 4;
            int gr = row0 + m;
            float4 v = make_float4(0.f, 0.f, 0.f, 0.f);
            if (gr < M) v = *(const float4*)(A + (size_t)gr * K + kt + k0);
            uint32_t h0 = pack_bf2(v.x, v.y), h1 = pack_bf2(v.z, v.w);
            float rx = v.x - __bfloat162float(((__nv_bfloat162*)&h0)->x);
            float ry = v.y - __bfloat162float(((__nv_bfloat162*)&h0)->y);
            float rz = v.z - __bfloat162float(((__nv_bfloat162*)&h1)->x);
            float rw = v.w - __bfloat162float(((__nv_bfloat162*)&h1)->y);
            uint32_t l0 = pack_bf2(rx, ry), l1 = pack_bf2(rz, rw);
            int off = m * RS + (k0 >> 3) * 8 + (k0 & 7);  // elems
            *(uint2*)(Ahi + off) = make_uint2(h0, h1);
            *(uint2*)(Alo + off) = make_uint2(l0, l1);
        }
        // ---- load B tile: 64 n x 32 k, transposed gather from B[K,Nc] ----
        #pragma unroll
        for (int i = tid; i < BK * BN; i += 256) {       // 2048
            int k = i >> 6, n = i & 63;
            int gc = col0 + n;
            float v = (gc < Nc) ? B[(size_t)(kt + k) * Nc + gc] : 0.f;
            __nv_bfloat16 h = __float2bfloat16(v);
            __nv_bfloat16 l = __float2bfloat16(v - __bfloat162float(h));
            int off = n * RS + (k >> 3) * 8 + (k & 7);
            Bhi[off] = h;
            Blo[off] = l;
        }
        __syncthreads();

        // ---- compute: 2 k-steps of k16 ----
        #pragma unroll
        for (int s = 0; s < 2; s++) {
            int kc = 2 * s;
            uint32_t ah0[4], ah1[4], al0[4], al1[4];
            {
                uint32_t base = (uint32_t)(((wm * 32 + aRow) * RS + (kc + aChk) * 8) * 2);
                ldsm4(ah0[0], ah0[1], ah0[2], ah0[3], uAhi + base);
                ldsm4(al0[0], al0[1], al0[2], al0[3], uAlo + base);
                uint32_t base1 = base + (uint32_t)(16 * RS * 2);
                ldsm4(ah1[0], ah1[1], ah1[2], ah1[3], uAhi + base1);
                ldsm4(al1[0], al1[1], al1[2], al1[3], uAlo + base1);
            }
            uint32_t bh_a[4], bh_b[4], bl_a[4], bl_b[4];
            {
                uint32_t base = (uint32_t)(((wn * 32 + lane) * RS + kc * 8) * 2);
                ldsm4(bh_a[0], bh_a[1], bh_a[2], bh_a[3], uBhi + base);
                ldsm4(bl_a[0], bl_a[1], bl_a[2], bl_a[3], uBlo + base);
                uint32_t base1 = base + 16;   // next 16B chunk (kc+1)
                ldsm4(bh_b[0], bh_b[1], bh_b[2], bh_b[3], uBhi + base1);
                ldsm4(bl_b[0], bl_b[1], bl_b[2], bl_b[3], uBlo + base1);
            }
            #pragma unroll
            for (int ni = 0; ni < 4; ni++) {
                uint32_t bh[2] = {bh_a[ni], bh_b[ni]};
                uint32_t bl[2] = {bl_a[ni], bl_b[ni]};
                mma_bf16(acc[0][ni], ah0, bh);
                mma_bf16(acc[0][ni], ah0, bl);
                mma_bf16(acc[0][ni], al0, bh);
                mma_bf16(acc[1][ni], ah1, bh);
                mma_bf16(acc[1][ni], ah1, bl);
                mma_bf16(acc[1][ni], al1, bh);
            }
        }
        __syncthreads();
    }

    // ---- epilogue ----
    int lq = lane >> 2, lr = lane & 3;
    #pragma unroll
    for (int mi = 0; mi < 2; mi++) {
        int r0 = row0 + wm * 32 + mi * 16 + lq;
        #pragma unroll
        for (int ni = 0; ni < 4; ni++) {
            int c = col0 + wn * 32 + ni * 8 + lr * 2;
            if (c + 1 < Nc || c + 1 < Nc) {}
            if (c < Nc) {
                float b0 = bias ? bias[c] : 0.f;
                float b1 = bias ? bias[c + 1] : 0.f;
                if (r0 < M)
                    *(float2*)(C + (size_t)r0 * Nc + c) =
                        make_float2(acc[mi][ni][0] + b0, acc[mi][ni][1] + b1);
                if (r0 + 8 < M)
                    *(float2*)(C + (size_t)(r0 + 8) * Nc + c) =
                        make_float2(acc[mi][ni][2] + b0, acc[mi][ni][3] + b1);
            }
        }
    }
}

// ---------------- per-node attention projections (warp per node) ----------------
__global__ void alpha_kernel(const float* __restrict__ h, const float* __restrict__ asrc,
                             const float* __restrict__ adst) {
    int gw = (blockIdx.x * blockDim.x + threadIdx.x) >> 5;
    int lane = threadIdx.x & 31;
    if (gw >= NN) return;
    const float* hp = h + (size_t)gw * HC;
    float s[3], d[3];
    #pragma unroll
    for (int hh = 0; hh < 3; hh++) {
        int c0 = hh * 64 + lane, c1 = c0 + 32;
        float v0 = hp[c0], v1 = hp[c1];
        s[hh] = wsum(v0 * asrc[c0] + v1 * asrc[c1]);
        d[hh] = wsum(v0 * adst[c0] + v1 * adst[c1]);
    }
    if (lane == 0) {
        g_as[gw * 3 + 0] = s[0]; g_as[gw * 3 + 1] = s[1]; g_as[gw * 3 + 2] = s[2];
        g_ad[gw * 3 + 0] = d[0]; g_ad[gw * 3 + 1] = d[1]; g_ad[gw * 3 + 2] = d[2];
    }
}

// ---------------- GAT aggregation: warp per destination, no atomics ----------------
__global__ void agg_kernel(const float* __restrict__ h, const float* __restrict__ bias,
                           float* __restrict__ out) {
    int gw = (blockIdx.x * blockDim.x + threadIdx.x) >> 5;
    int lane = threadIdx.x & 31;
    if (gw >= NN) return;
    int beg = g_rowptr[gw], end = g_rowptr[gw + 1];
    float ad0 = g_ad[gw * 3 + 0], ad1 = g_ad[gw * 3 + 1], ad2 = g_ad[gw * 3 + 2];

    float m0 = -1e30f, m1 = -1e30f, m2 = -1e30f;
    for (int i = beg + lane; i < end; i += 32) {
        int s = g_srcs[i];
        m0 = fmaxf(m0, lrelu(g_as[s * 3 + 0] + ad0));
        m1 = fmaxf(m1, lrelu(g_as[s * 3 + 1] + ad1));
        m2 = fmaxf(m2, lrelu(g_as[s * 3 + 2] + ad2));
    }
    m0 = wmax(m0); m1 = wmax(m1); m2 = wmax(m2);

    float d0 = 0.f, d1 = 0.f, d2 = 0.f;
    for (int i = beg + lane; i < end; i += 32) {
        int s = g_srcs[i];
        d0 += __expf(lrelu(g_as[s * 3 + 0] + ad0) - m0);
        d1 += __expf(lrelu(g_as[s * 3 + 1] + ad1) - m1);
        d2 += __expf(lrelu(g_as[s * 3 + 2] + ad2) - m2);
    }
    d0 = wsum(d0); d1 = wsum(d1); d2 = wsum(d2);
    float i0 = 1.f / (d0 + 1e-16f), i1 = 1.f / (d1 + 1e-16f), i2 = 1.f / (d2 + 1e-16f);

    float a0c0 = 0.f, a0c1 = 0.f, a1c0 = 0.f, a1c1 = 0.f, a2c0 = 0.f, a2c1 = 0.f;
    for (int i = beg; i < end; i++) {
        int s = g_srcs[i];
        float w0 = __expf(lrelu(g_as[s * 3 + 0] + ad0) - m0) * i0;
        float w1 = __expf(lrelu(g_as[s * 3 + 1] + ad1) - m1) * i1;
        float w2 = __expf(lrelu(g_as[s * 3 + 2] + ad2) - m2) * i2;
        const float* hs = h + (size_t)s * HC;
        a0c0 += hs[lane +   0] * w0;
        a0c1 += hs[lane +  32] * w0;
        a1c0 += hs[lane +  64] * w1;
        a1c1 += hs[lane +  96] * w1;
        a2c0 += hs[lane + 128] * w2;
        a2c1 += hs[lane + 160] * w2;
    }
    float* op = out + (size_t)gw * HC;
    op[lane +   0] = elu_f(a0c0 + bias[lane +   0]);
    op[lane +  32] = elu_f(a0c1 + bias[lane +  32]);
    op[lane +  64] = elu_f(a1c0 + bias[lane +  64]);
    op[lane +  96] = elu_f(a1c1 + bias[lane +  96]);
    op[lane + 128] = elu_f(a2c0 + bias[lane + 128]);
    op[lane + 160] = elu_f(a2c1 + bias[lane + 160]);
}

// ---------------- launch ----------------
extern "C" void kernel_launch(void* const* d_in, const int* in_sizes, int n_in,
                              void* d_out, int out_size) {
    const float* x     = (const float*)d_in[0];
    const int*   ei    = (const int*)  d_in[1];
    const float* W1    = (const float*)d_in[2];
    const float* asrc1 = (const float*)d_in[3];
    const float* adst1 = (const float*)d_in[4];
    const float* b1    = (const float*)d_in[5];
    const float* W2    = (const float*)d_in[6];
    const float* asrc2 = (const float*)d_in[7];
    const float* adst2 = (const float*)d_in[8];
    const float* b2    = (const float*)d_in[9];
    const float* Wf1   = (const float*)d_in[10];
    const float* bf1   = (const float*)d_in[11];
    const float* Wf2   = (const float*)d_in[12];
    const float* bf2   = (const float*)d_in[13];
    float* out = (float*)d_out;

    float *h, *hx, *wf, *bf;
    cudaGetSymbolAddress((void**)&h,  g_h);
    cudaGetSymbolAddress((void**)&hx, g_hx);
    cudaGetSymbolAddress((void**)&wf, g_wf);
    cudaGetSymbolAddress((void**)&bf, g_bf);

    const int* srcp = ei;
    const int* dstp = ei + EE;

    // CSR build + MLP weight collapse
    zero_kernel<<<(NN + 255) / 256, 256>>>();
    count_kernel<<<(ET + 255) / 256, 256>>>(dstp);
    scan_kernel<<<1, 1024>>>();
    bucket_kernel<<<(ET + 255) / 256, 256>>>(srcp, dstp);
    fuse_mlp_kernel<<<(HC * OUTC + OUTC + 255) / 256, 256>>>(Wf1, bf1, Wf2, bf2);

    int warpBlocks = (NN * 32 + 255) / 256;
    int gy = (NN + BM - 1) / BM;

    // layer 1
    gemm_bf16<<<dim3(HC / BN, gy), 256>>>(x, W1, nullptr, h, NN, INC, HC);
    alpha_kernel<<<warpBlocks, 256>>>(h, asrc1, adst1);
    agg_kernel<<<warpBlocks, 256>>>(h, b1, hx);

    // layer 2
    gemm_bf16<<<dim3(HC / BN, gy), 256>>>(hx, W2, nullptr, h, NN, HC, HC);
    alpha_kernel<<<warpBlocks, 256>>>(h, asrc2, adst2);
    agg_kernel<<<warpBlocks, 256>>>(h, b2, hx);

    // fused MLP head (single GEMM, Nc=32)
    gemm_bf16<<<dim3(1, gy), 256>>>(hx, wf, bf, out, NN, HC, OUTC);
}

// round 5
// speedup vs baseline: 1.9999x; 1.0696x over previous
#include <cuda_runtime.h>
#include <cuda_bf16.h>
#include <math.h>
#include <stdint.h>

#define NN   50000
#define EE   800000
#define ET   (EE + NN)
#define INC  128
#define HC   192
#define OUTC 32

// ---------------- scratch ----------------
__device__ float g_h[NN * HC];
__device__ __nv_bfloat16 g_xhi[NN * INC], g_xlo[NN * INC];
__device__ __nv_bfloat16 g_hxhi[NN * HC], g_hxlo[NN * HC];
__device__ __nv_bfloat16 g_w1thi[HC * INC], g_w1tlo[HC * INC];
__device__ __nv_bfloat16 g_w2thi[HC * HC],  g_w2tlo[HC * HC];
__device__ __nv_bfloat16 g_wfthi[OUTC * HC], g_wftlo[OUTC * HC];
__device__ float g_bf[OUTC];
__device__ float g_as[NN * 3];
__device__ float g_ad[NN * 3];
__device__ int   g_deg[NN];
__device__ int   g_ctr[NN];
__device__ int   g_rowptr[NN + 1];
__device__ int   g_srcs[ET];

// ---------------- helpers ----------------
__device__ __forceinline__ float lrelu(float v) { return v > 0.f ? v : 0.2f * v; }
__device__ __forceinline__ float elu_f(float v) { return v > 0.f ? v : expm1f(v); }
__device__ __forceinline__ float wmax(float v) {
    #pragma unroll
    for (int o = 16; o > 0; o >>= 1) v = fmaxf(v, __shfl_xor_sync(0xffffffffu, v, o));
    return v;
}
__device__ __forceinline__ float wsum(float v) {
    #pragma unroll
    for (int o = 16; o > 0; o >>= 1) v += __shfl_xor_sync(0xffffffffu, v, o);
    return v;
}
__device__ __forceinline__ uint32_t smem_u32(const void* p) {
    uint32_t a;
    asm("{ .reg .u64 t; cvta.to.shared.u64 t, %1; cvt.u32.u64 %0, t; }" : "=r"(a) : "l"(p));
    return a;
}
__device__ __forceinline__ void ldsm4(uint32_t& r0, uint32_t& r1, uint32_t& r2, uint32_t& r3, uint32_t a) {
    asm volatile("ldmatrix.sync.aligned.m8n8.x4.shared.b16 {%0,%1,%2,%3}, [%4];"
                 : "=r"(r0), "=r"(r1), "=r"(r2), "=r"(r3) : "r"(a));
}
__device__ __forceinline__ void mma_bf16(float* c, const uint32_t* a, const uint32_t* b) {
    asm volatile(
        "mma.sync.aligned.m16n8k16.row.col.f32.bf16.bf16.f32 "
        "{%0,%1,%2,%3}, {%4,%5,%6,%7}, {%8,%9}, {%0,%1,%2,%3};"
        : "+f"(c[0]), "+f"(c[1]), "+f"(c[2]), "+f"(c[3])
        : "r"(a[0]), "r"(a[1]), "r"(a[2]), "r"(a[3]), "r"(b[0]), "r"(b[1]));
}
__device__ __forceinline__ void cpasync16(uint32_t dst, const void* src, bool pred) {
    int sz = pred ? 16 : 0;
    asm volatile("cp.async.cg.shared.global [%0], [%1], 16, %2;"
                 :: "r"(dst), "l"(src), "r"(sz) : "memory");
}
__device__ __forceinline__ void cp_commit() { asm volatile("cp.async.commit_group;" ::: "memory"); }
template <int N>
__device__ __forceinline__ void cp_wait() { asm volatile("cp.async.wait_group %0;" :: "n"(N) : "memory"); }

// ---------------- CSR build ----------------
__global__ void zero_kernel() {
    int i = blockIdx.x * blockDim.x + threadIdx.x;
    if (i < NN) { g_deg[i] = 0; g_ctr[i] = 0; }
}
__global__ void zero_alpha_kernel() {
    int i = blockIdx.x * blockDim.x + threadIdx.x;
    if (i < NN * 3) { g_as[i] = 0.f; g_ad[i] = 0.f; }
}
__global__ void count_kernel(const int* __restrict__ dst) {
    int i = blockIdx.x * blockDim.x + threadIdx.x;
    if (i >= ET) return;
    int d = (i < EE) ? dst[i] : (i - EE);
    atomicAdd(&g_deg[d], 1);
}
__global__ void scan_kernel() {
    __shared__ int part[1024];
    const int per = (NN + 1023) / 1024;
    int t = threadIdx.x;
    int start = t * per, end = min(start + per, NN);
    int s = 0;
    for (int i = start; i < end; i++) s += g_deg[i];
    part[t] = s;
    __syncthreads();
    for (int off = 1; off < 1024; off <<= 1) {
        int v = (t >= off) ? part[t - off] : 0;
        __syncthreads();
        part[t] += v;
        __syncthreads();
    }
    int run = part[t] - s;
    for (int i = start; i < end; i++) { g_rowptr[i] = run; run += g_deg[i]; }
    if (t == 1023) g_rowptr[NN] = part[1023];
}
__global__ void bucket_kernel(const int* __restrict__ src, const int* __restrict__ dst) {
    int i = blockIdx.x * blockDim.x + threadIdx.x;
    if (i >= ET) return;
    int s, d;
    if (i < EE) { s = src[i]; d = dst[i]; } else { s = i - EE; d = s; }
    int pos = atomicAdd(&g_ctr[d], 1);
    g_srcs[g_rowptr[d] + pos] = s;
}

// ---------------- operand prep ----------------
// elementwise fp32 -> bf16 hi/lo (n multiple of 4)
__global__ void split_kernel(const float* __restrict__ in, __nv_bfloat16* __restrict__ hi,
                             __nv_bfloat16* __restrict__ lo, int n4) {
    int i = blockIdx.x * blockDim.x + threadIdx.x;
    if (i >= n4) return;
    float4 v = ((const float4*)in)[i];
    float vv[4] = {v.x, v.y, v.z, v.w};
    __nv_bfloat16 h[4], l[4];
    #pragma unroll
    for (int j = 0; j < 4; j++) {
        h[j] = __float2bfloat16(vv[j]);
        l[j] = __float2bfloat16(vv[j] - __bfloat162float(h[j]));
    }
    ((ushort4*)hi)[i] = make_ushort4(*(uint16_t*)&h[0], *(uint16_t*)&h[1], *(uint16_t*)&h[2], *(uint16_t*)&h[3]);
    ((ushort4*)lo)[i] = make_ushort4(*(uint16_t*)&l[0], *(uint16_t*)&l[1], *(uint16_t*)&l[2], *(uint16_t*)&l[3]);
}
// W[K][Nc] -> transposed split tables [Nc][K]
__global__ void wsplit_kernel(const float* __restrict__ W, __nv_bfloat16* __restrict__ thi,
                              __nv_bfloat16* __restrict__ tlo, int K, int Nc) {
    int i = blockIdx.x * blockDim.x + threadIdx.x;
    if (i >= K * Nc) return;
    int k = i / Nc, c = i - k * Nc;
    float v = W[i];
    __nv_bfloat16 h = __float2bfloat16(v);
    thi[c * K + k] = h;
    tlo[c * K + k] = __float2bfloat16(v - __bfloat162float(h));
}
// Wf = Wf1@Wf2 (transposed split), bf = bf1@Wf2 + bf2
__global__ void fuse_mlp_kernel(const float* __restrict__ Wf1, const float* __restrict__ bf1,
                                const float* __restrict__ Wf2, const float* __restrict__ bf2) {
    int i = blockIdx.x * blockDim.x + threadIdx.x;
    if (i < HC * OUTC) {
        int r = i >> 5, c = i & 31;
        float s = 0.f;
        #pragma unroll 8
        for (int j = 0; j < 64; j++) s += Wf1[r * 64 + j] * Wf2[j * OUTC + c];
        __nv_bfloat16 h = __float2bfloat16(s);
        g_wfthi[c * HC + r] = h;
        g_wftlo[c * HC + r] = __float2bfloat16(s - __bfloat162float(h));
    } else if (i < HC * OUTC + OUTC) {
        int c = i - HC * OUTC;
        float s = bf2[c];
        for (int j = 0; j < 64; j++) s += bf1[j] * Wf2[j * OUTC + c];
        g_bf[c] = s;
    }
}

// ---------------- bf16-split tensor-core GEMM, double-buffered cp.async ----------------
// C[M,Nc] = A[M,K] @ Bt[Nc,K]^T (+bias). A,Bt pre-split bf16 tables.
// Tile 128x64x32, 256 threads (8 warps: 4M x 2N). Optional fused alpha projections.
#define BM 128
#define BN 64
#define BK 32
#define RS 40   // smem row stride in bf16 elems (80B)
// stage layout (bf16 elems)
#define SA_HI 0
#define SA_LO 5120
#define SB_HI 10240
#define SB_LO 12800
#define STAGE 15360
#define SMEMB (2 * STAGE * 2)   // 61440 bytes

template <bool FUSE>
__global__ void __launch_bounds__(256) gemm_bf16(const __nv_bfloat16* __restrict__ Ahi,
                                                 const __nv_bfloat16* __restrict__ Alo,
                                                 const __nv_bfloat16* __restrict__ Bthi,
                                                 const __nv_bfloat16* __restrict__ Btlo,
                                                 const float* __restrict__ bias,
                                                 float* __restrict__ C,
                                                 const float* __restrict__ asrc,
                                                 const float* __restrict__ adst,
                                                 int M, int K, int Nc) {
    extern __shared__ __nv_bfloat16 smem[];
    uint32_t sbase = smem_u32(smem);

    int tid = threadIdx.x;
    int lane = tid & 31, warp = tid >> 5;
    int wm = warp & 3, wn = warp >> 2;
    int row0 = blockIdx.y * BM, col0 = blockIdx.x * BN;

    int aRow = ((lane & 8) ? 8 : 0) + (lane & 7);
    int aChk = (lane & 16) ? 1 : 0;

    float acc[2][4][4];
    #pragma unroll
    for (int i = 0; i < 2; i++)
        #pragma unroll
        for (int j = 0; j < 4; j++)
            #pragma unroll
            for (int k = 0; k < 4; k++) acc[i][j][k] = 0.f;

    const int ntiles = K / BK;

    // ---- async load of one stage ----
    auto load_stage = [&](int t, int st) {
        uint32_t sb = sbase + (uint32_t)(st * STAGE * 2);
        int kt = t * BK;
        // A: 128 rows x 4 chunks, hi+lo  (512 ops each table, 2 per thread)
        #pragma unroll
        for (int j = 0; j < 2; j++) {
            int idx = tid + j * 256;
            int r = idx >> 2, ch = idx & 3;
            int gr = row0 + r;
            bool p = gr < M;
            size_t go = (size_t)gr * K + kt + ch * 8;
            uint32_t dof = (uint32_t)((r * RS + ch * 8) * 2);
            cpasync16(sb + SA_HI * 2 + dof, Ahi + go, p);
            cpasync16(sb + SA_LO * 2 + dof, Alo + go, p);
        }
        // B: 64 rows x 4 chunks, hi+lo (256 ops each table, 1 per thread)
        {
            int r = tid >> 2, ch = tid & 3;
            int gc = col0 + r;
            bool p = gc < Nc;
            size_t go = (size_t)gc * K + kt + ch * 8;
            uint32_t dof = (uint32_t)((r * RS + ch * 8) * 2);
            cpasync16(sb + SB_HI * 2 + dof, Bthi + go, p);
            cpasync16(sb + SB_LO * 2 + dof, Btlo + go, p);
        }
        cp_commit();
    };

    load_stage(0, 0);

    for (int t = 0; t < ntiles; t++) {
        if (t + 1 < ntiles) { load_stage(t + 1, (t + 1) & 1); cp_wait<1>(); }
        else cp_wait<0>();
        __syncthreads();

        uint32_t sb = sbase + (uint32_t)((t & 1) * STAGE * 2);
        uint32_t uAhi = sb + SA_HI * 2, uAlo = sb + SA_LO * 2;
        uint32_t uBhi = sb + SB_HI * 2, uBlo = sb + SB_LO * 2;

        #pragma unroll
        for (int s = 0; s < 2; s++) {
            int kc = 2 * s;
            uint32_t ah0[4], ah1[4], al0[4], al1[4];
            {
                uint32_t base = (uint32_t)(((wm * 32 + aRow) * RS + (kc + aChk) * 8) * 2);
                ldsm4(ah0[0], ah0[1], ah0[2], ah0[3], uAhi + base);
                ldsm4(al0[0], al0[1], al0[2], al0[3], uAlo + base);
                uint32_t base1 = base + (uint32_t)(16 * RS * 2);
                ldsm4(ah1[0], ah1[1], ah1[2], ah1[3], uAhi + base1);
                ldsm4(al1[0], al1[1], al1[2], al1[3], uAlo + base1);
            }
            uint32_t bh_a[4], bh_b[4], bl_a[4], bl_b[4];
            {
                uint32_t base = (uint32_t)(((wn * 32 + lane) * RS + kc * 8) * 2);
                ldsm4(bh_a[0], bh_a[1], bh_a[2], bh_a[3], uBhi + base);
                ldsm4(bl_a[0], bl_a[1], bl_a[2], bl_a[3], uBlo + base);
                uint32_t base1 = base + 16;
                ldsm4(bh_b[0], bh_b[1], bh_b[2], bh_b[3], uBhi + base1);
                ldsm4(bl_b[0], bl_b[1], bl_b[2], bl_b[3], uBlo + base1);
            }
            #pragma unroll
            for (int ni = 0; ni < 4; ni++) {
                uint32_t bh[2] = {bh_a[ni], bh_b[ni]};
                uint32_t bl[2] = {bl_a[ni], bl_b[ni]};
                mma_bf16(acc[0][ni], ah0, bh);
                mma_bf16(acc[0][ni], ah0, bl);
                mma_bf16(acc[0][ni], al0, bh);
                mma_bf16(acc[1][ni], ah1, bh);
                mma_bf16(acc[1][ni], ah1, bl);
                mma_bf16(acc[1][ni], al1, bh);
            }
        }
        __syncthreads();
    }

    // ---- epilogue: C store (+bias) ----
    int lq = lane >> 2, lr = lane & 3;
    #pragma unroll
    for (int mi = 0; mi < 2; mi++) {
        int r0 = row0 + wm * 32 + mi * 16 + lq;
        #pragma unroll
        for (int ni = 0; ni < 4; ni++) {
            int c = col0 + wn * 32 + ni * 8 + lr * 2;
            if (c < Nc) {
                float b0 = bias ? bias[c] : 0.f;
                float b1 = bias ? bias[c + 1] : 0.f;
                if (r0 < M)
                    *(float2*)(C + (size_t)r0 * Nc + c) =
                        make_float2(acc[mi][ni][0] + b0, acc[mi][ni][1] + b1);
                if (r0 + 8 < M)
                    *(float2*)(C + (size_t)(r0 + 8) * Nc + c) =
                        make_float2(acc[mi][ni][2] + b0, acc[mi][ni][3] + b1);
            }
        }
    }

    // ---- fused alpha projections: partial dots + quad reduce + atomics ----
    if (FUSE) {
        int head = (col0 + wn * 32) >> 6;
        #pragma unroll
        for (int mi = 0; mi < 2; mi++) {
            int r0 = row0 + wm * 32 + mi * 16 + lq;
            float s0 = 0.f, s1 = 0.f, d0 = 0.f, d1 = 0.f;
            #pragma unroll
            for (int ni = 0; ni < 4; ni++) {
                int c = col0 + wn * 32 + ni * 8 + lr * 2;
                float ws0 = asrc[c], ws1 = asrc[c + 1];
                float wd0 = adst[c], wd1 = adst[c + 1];
                s0 += acc[mi][ni][0] * ws0 + acc[mi][ni][1] * ws1;
                s1 += acc[mi][ni][2] * ws0 + acc[mi][ni][3] * ws1;
                d0 += acc[mi][ni][0] * wd0 + acc[mi][ni][1] * wd1;
                d1 += acc[mi][ni][2] * wd0 + acc[mi][ni][3] * wd1;
            }
            #pragma unroll
            for (int o = 1; o <= 2; o <<= 1) {
                s0 += __shfl_xor_sync(0xffffffffu, s0, o);
                s1 += __shfl_xor_sync(0xffffffffu, s1, o);
                d0 += __shfl_xor_sync(0xffffffffu, d0, o);
                d1 += __shfl_xor_sync(0xffffffffu, d1, o);
            }
            if (lr == 0) {
                if (r0 < M) {
                    atomicAdd(&g_as[r0 * 3 + head], s0);
                    atomicAdd(&g_ad[r0 * 3 + head], d0);
                }
                if (r0 + 8 < M) {
                    atomicAdd(&g_as[(r0 + 8) * 3 + head], s1);
                    atomicAdd(&g_ad[(r0 + 8) * 3 + head], d1);
                }
            }
        }
    }
}

// ---------------- GAT aggregation: warp per destination, writes bf16 hi/lo ----------------
__global__ void agg_kernel(const float* __restrict__ h, const float* __restrict__ bias,
                           __nv_bfloat16* __restrict__ ohi, __nv_bfloat16* __restrict__ olo) {
    int gw = (blockIdx.x * blockDim.x + threadIdx.x) >> 5;
    int lane = threadIdx.x & 31;
    if (gw >= NN) return;
    int beg = g_rowptr[gw], end = g_rowptr[gw + 1];
    float ad0 = g_ad[gw * 3 + 0], ad1 = g_ad[gw * 3 + 1], ad2 = g_ad[gw * 3 + 2];

    float m0 = -1e30f, m1 = -1e30f, m2 = -1e30f;
    for (int i = beg + lane; i < end; i += 32) {
        int s = g_srcs[i];
        m0 = fmaxf(m0, lrelu(g_as[s * 3 + 0] + ad0));
        m1 = fmaxf(m1, lrelu(g_as[s * 3 + 1] + ad1));
        m2 = fmaxf(m2, lrelu(g_as[s * 3 + 2] + ad2));
    }
    m0 = wmax(m0); m1 = wmax(m1); m2 = wmax(m2);

    float d0 = 0.f, d1 = 0.f, d2 = 0.f;
    for (int i = beg + lane; i < end; i += 32) {
        int s = g_srcs[i];
        d0 += __expf(lrelu(g_as[s * 3 + 0] + ad0) - m0);
        d1 += __expf(lrelu(g_as[s * 3 + 1] + ad1) - m1);
        d2 += __expf(lrelu(g_as[s * 3 + 2] + ad2) - m2);
    }
    d0 = wsum(d0); d1 = wsum(d1); d2 = wsum(d2);
    float i0 = 1.f / (d0 + 1e-16f), i1 = 1.f / (d1 + 1e-16f), i2 = 1.f / (d2 + 1e-16f);

    float a0c0 = 0.f, a0c1 = 0.f, a1c0 = 0.f, a1c1 = 0.f, a2c0 = 0.f, a2c1 = 0.f;
    for (int i = beg; i < end; i++) {
        int s = g_srcs[i];
        float w0 = __expf(lrelu(g_as[s * 3 + 0] + ad0) - m0) * i0;
        float w1 = __expf(lrelu(g_as[s * 3 + 1] + ad1) - m1) * i1;
        float w2 = __expf(lrelu(g_as[s * 3 + 2] + ad2) - m2) * i2;
        const float* hs = h + (size_t)s * HC;
        a0c0 += hs[lane +   0] * w0;
        a0c1 += hs[lane +  32] * w0;
        a1c0 += hs[lane +  64] * w1;
        a1c1 += hs[lane +  96] * w1;
        a2c0 += hs[lane + 128] * w2;
        a2c1 += hs[lane + 160] * w2;
    }
    float vals[6] = {a0c0, a0c1, a1c0, a1c1, a2c0, a2c1};
    #pragma unroll
    for (int q = 0; q < 6; q++) {
        int col = q * 32 + lane;
        float v = elu_f(vals[q] + bias[col]);
        __nv_bfloat16 hh = __float2bfloat16(v);
        size_t idx = (size_t)gw * HC + col;
        ohi[idx] = hh;
        olo[idx] = __float2bfloat16(v - __bfloat162float(hh));
    }
}

// ---------------- launch ----------------
extern "C" void kernel_launch(void* const* d_in, const int* in_sizes, int n_in,
                              void* d_out, int out_size) {
    const float* x     = (const float*)d_in[0];
    const int*   ei    = (const int*)  d_in[1];
    const float* W1    = (const float*)d_in[2];
    const float* asrc1 = (const float*)d_in[3];
    const float* adst1 = (const float*)d_in[4];
    const float* b1    = (const float*)d_in[5];
    const float* W2    = (const float*)d_in[6];
    const float* asrc2 = (const float*)d_in[7];
    const float* adst2 = (const float*)d_in[8];
    const float* b2    = (const float*)d_in[9];
    const float* Wf1   = (const float*)d_in[10];
    const float* bf1   = (const float*)d_in[11];
    const float* Wf2   = (const float*)d_in[12];
    const float* bf2   = (const float*)d_in[13];
    float* out = (float*)d_out;

    float *h, *bf;
    __nv_bfloat16 *xhi, *xlo, *hxhi, *hxlo, *w1thi, *w1tlo, *w2thi, *w2tlo, *wfthi, *wftlo;
    cudaGetSymbolAddress((void**)&h,     g_h);
    cudaGetSymbolAddress((void**)&bf,    g_bf);
    cudaGetSymbolAddress((void**)&xhi,   g_xhi);
    cudaGetSymbolAddress((void**)&xlo,   g_xlo);
    cudaGetSymbolAddress((void**)&hxhi,  g_hxhi);
    cudaGetSymbolAddress((void**)&hxlo,  g_hxlo);
    cudaGetSymbolAddress((void**)&w1thi, g_w1thi);
    cudaGetSymbolAddress((void**)&w1tlo, g_w1tlo);
    cudaGetSymbolAddress((void**)&w2thi, g_w2thi);
    cudaGetSymbolAddress((void**)&w2tlo, g_w2tlo);
    cudaGetSymbolAddress((void**)&wfthi, g_wfthi);
    cudaGetSymbolAddress((void**)&wftlo, g_wftlo);

    const int* srcp = ei;
    const int* dstp = ei + EE;

    cudaFuncSetAttribute(gemm_bf16<true>,  cudaFuncAttributeMaxDynamicSharedMemorySize, SMEMB);
    cudaFuncSetAttribute(gemm_bf16<false>, cudaFuncAttributeMaxDynamicSharedMemorySize, SMEMB);

    // CSR build + operand prep
    zero_kernel<<<(NN + 255) / 256, 256>>>();
    count_kernel<<<(ET + 255) / 256, 256>>>(dstp);
    scan_kernel<<<1, 1024>>>();
    bucket_kernel<<<(ET + 255) / 256, 256>>>(srcp, dstp);
    split_kernel<<<(NN * INC / 4 + 255) / 256, 256>>>(x, xhi, xlo, NN * INC / 4);
    wsplit_kernel<<<(INC * HC + 255) / 256, 256>>>(W1, w1thi, w1tlo, INC, HC);
    wsplit_kernel<<<(HC * HC + 255) / 256, 256>>>(W2, w2thi, w2tlo, HC, HC);
    fuse_mlp_kernel<<<(HC * OUTC + OUTC + 255) / 256, 256>>>(Wf1, bf1, Wf2, bf2);

    int warpBlocks = (NN * 32 + 255) / 256;
    int gy = (NN + BM - 1) / BM;
    int zaBlocks = (NN * 3 + 255) / 256;

    // layer 1
    zero_alpha_kernel<<<zaBlocks, 256>>>();
    gemm_bf16<true><<<dim3(HC / BN, gy), 256, SMEMB>>>(xhi, xlo, w1thi, w1tlo, nullptr, h,
                                                       asrc1, adst1, NN, INC, HC);
    agg_kernel<<<warpBlocks, 256>>>(h, b1, hxhi, hxlo);

    // layer 2
    zero_alpha_kernel<<<zaBlocks, 256>>>();
    gemm_bf16<true><<<dim3(HC / BN, gy), 256, SMEMB>>>(hxhi, hxlo, w2thi, w2tlo, nullptr, h,
                                                       asrc2, adst2, NN, HC, HC);
    agg_kernel<<<warpBlocks, 256>>>(h, b2, hxhi, hxlo);

    // fused MLP head (single GEMM, Nc=32)
    gemm_bf16<false><<<dim3(1, gy), 256, SMEMB>>>(hxhi, hxlo, wfthi, wftlo, bf, out,
                                                  nullptr, nullptr, NN, HC, OUTC);
}

// round 6
// speedup vs baseline: 2.1226x; 1.0614x over previous
#include <cuda_runtime.h>
#include <cuda_bf16.h>
#include <cuda_fp16.h>
#include <math.h>
#include <stdint.h>

#define NN   50000
#define EE   800000
#define ET   (EE + NN)
#define INC  128
#define HC   192
#define OUTC 32

// ---------------- scratch ----------------
__device__ __half g_h[NN * HC];                       // fp16 h table (agg gather)
__device__ __nv_bfloat16 g_xhi[NN * INC], g_xlo[NN * INC];
__device__ __nv_bfloat16 g_hxhi[NN * HC], g_hxlo[NN * HC];
__device__ __nv_bfloat16 g_w1thi[HC * INC], g_w1tlo[HC * INC];
__device__ __nv_bfloat16 g_w2thi[HC * HC],  g_w2tlo[HC * HC];
__device__ __nv_bfloat16 g_wfthi[OUTC * HC], g_wftlo[OUTC * HC];
__device__ float g_bf[OUTC];
__device__ float g_as[NN * 3];
__device__ float g_ad[NN * 3];
__device__ int   g_deg[NN];
__device__ int   g_ctr[NN];
__device__ int   g_rowptr[NN + 1];
__device__ int   g_srcs[ET];

// ---------------- helpers ----------------
__device__ __forceinline__ float lrelu(float v) { return v > 0.f ? v : 0.2f * v; }
__device__ __forceinline__ float elu_f(float v) { return v > 0.f ? v : expm1f(v); }
__device__ __forceinline__ float wsum(float v) {
    #pragma unroll
    for (int o = 16; o > 0; o >>= 1) v += __shfl_xor_sync(0xffffffffu, v, o);
    return v;
}
__device__ __forceinline__ uint32_t smem_u32(const void* p) {
    uint32_t a;
    asm("{ .reg .u64 t; cvta.to.shared.u64 t, %1; cvt.u32.u64 %0, t; }" : "=r"(a) : "l"(p));
    return a;
}
__device__ __forceinline__ void ldsm4(uint32_t& r0, uint32_t& r1, uint32_t& r2, uint32_t& r3, uint32_t a) {
    asm volatile("ldmatrix.sync.aligned.m8n8.x4.shared.b16 {%0,%1,%2,%3}, [%4];"
                 : "=r"(r0), "=r"(r1), "=r"(r2), "=r"(r3) : "r"(a));
}
__device__ __forceinline__ void mma_bf16(float* c, const uint32_t* a, const uint32_t* b) {
    asm volatile(
        "mma.sync.aligned.m16n8k16.row.col.f32.bf16.bf16.f32 "
        "{%0,%1,%2,%3}, {%4,%5,%6,%7}, {%8,%9}, {%0,%1,%2,%3};"
        : "+f"(c[0]), "+f"(c[1]), "+f"(c[2]), "+f"(c[3])
        : "r"(a[0]), "r"(a[1]), "r"(a[2]), "r"(a[3]), "r"(b[0]), "r"(b[1]));
}
__device__ __forceinline__ void cpasync16(uint32_t dst, const void* src, bool pred) {
    int sz = pred ? 16 : 0;
    asm volatile("cp.async.cg.shared.global [%0], [%1], 16, %2;"
                 :: "r"(dst), "l"(src), "r"(sz) : "memory");
}
__device__ __forceinline__ void cp_commit() { asm volatile("cp.async.commit_group;" ::: "memory"); }
template <int N>
__device__ __forceinline__ void cp_wait() { asm volatile("cp.async.wait_group %0;" :: "n"(N) : "memory"); }

// ---------------- CSR build ----------------
__global__ void zero_kernel() {
    int i = blockIdx.x * blockDim.x + threadIdx.x;
    if (i < NN) { g_deg[i] = 0; g_ctr[i] = 0; }
}
__global__ void count_kernel(const int* __restrict__ dst) {
    int i = blockIdx.x * blockDim.x + threadIdx.x;
    if (i >= ET) return;
    int d = (i < EE) ? dst[i] : (i - EE);
    atomicAdd(&g_deg[d], 1);
}
__global__ void scan_kernel() {
    __shared__ int part[1024];
    const int per = (NN + 1023) / 1024;
    int t = threadIdx.x;
    int start = t * per, end = min(start + per, NN);
    int s = 0;
    for (int i = start; i < end; i++) s += g_deg[i];
    part[t] = s;
    __syncthreads();
    for (int off = 1; off < 1024; off <<= 1) {
        int v = (t >= off) ? part[t - off] : 0;
        __syncthreads();
        part[t] += v;
        __syncthreads();
    }
    int run = part[t] - s;
    for (int i = start; i < end; i++) { g_rowptr[i] = run; run += g_deg[i]; }
    if (t == 1023) g_rowptr[NN] = part[1023];
}
__global__ void bucket_kernel(const int* __restrict__ src, const int* __restrict__ dst) {
    int i = blockIdx.x * blockDim.x + threadIdx.x;
    if (i >= ET) return;
    int s, d;
    if (i < EE) { s = src[i]; d = dst[i]; } else { s = i - EE; d = s; }
    int pos = atomicAdd(&g_ctr[d], 1);
    g_srcs[g_rowptr[d] + pos] = s;
}

// ---------------- operand prep ----------------
__global__ void split_kernel(const float* __restrict__ in, __nv_bfloat16* __restrict__ hi,
                             __nv_bfloat16* __restrict__ lo, int n4) {
    int i = blockIdx.x * blockDim.x + threadIdx.x;
    if (i >= n4) return;
    float4 v = ((const float4*)in)[i];
    float vv[4] = {v.x, v.y, v.z, v.w};
    __nv_bfloat16 h[4], l[4];
    #pragma unroll
    for (int j = 0; j < 4; j++) {
        h[j] = __float2bfloat16(vv[j]);
        l[j] = __float2bfloat16(vv[j] - __bfloat162float(h[j]));
    }
    ((ushort4*)hi)[i] = make_ushort4(*(uint16_t*)&h[0], *(uint16_t*)&h[1], *(uint16_t*)&h[2], *(uint16_t*)&h[3]);
    ((ushort4*)lo)[i] = make_ushort4(*(uint16_t*)&l[0], *(uint16_t*)&l[1], *(uint16_t*)&l[2], *(uint16_t*)&l[3]);
}
__global__ void wsplit_kernel(const float* __restrict__ W, __nv_bfloat16* __restrict__ thi,
                              __nv_bfloat16* __restrict__ tlo, int K, int Nc) {
    int i = blockIdx.x * blockDim.x + threadIdx.x;
    if (i >= K * Nc) return;
    int k = i / Nc, c = i - k * Nc;
    float v = W[i];
    __nv_bfloat16 h = __float2bfloat16(v);
    thi[c * K + k] = h;
    tlo[c * K + k] = __float2bfloat16(v - __bfloat162float(h));
}
__global__ void fuse_mlp_kernel(const float* __restrict__ Wf1, const float* __restrict__ bf1,
                                const float* __restrict__ Wf2, const float* __restrict__ bf2) {
    int i = blockIdx.x * blockDim.x + threadIdx.x;
    if (i < HC * OUTC) {
        int r = i >> 5, c = i & 31;
        float s = 0.f;
        #pragma unroll 8
        for (int j = 0; j < 64; j++) s += Wf1[r * 64 + j] * Wf2[j * OUTC + c];
        __nv_bfloat16 h = __float2bfloat16(s);
        g_wfthi[c * HC + r] = h;
        g_wftlo[c * HC + r] = __float2bfloat16(s - __bfloat162float(h));
    } else if (i < HC * OUTC + OUTC) {
        int c = i - HC * OUTC;
        float s = bf2[c];
        for (int j = 0; j < 64; j++) s += bf1[j] * Wf2[j * OUTC + c];
        g_bf[c] = s;
    }
}

// ---------------- bf16-split tensor-core GEMM, double-buffered cp.async ----------------
// OUT16: C is fp16 (__half, no bias). else fp32 (+bias).
// FUSE: fused alpha projections (head = col tile, atomic-free smem reduce).
#define BM 128
#define BN 64
#define BK 32
#define RS 40
#define SA_HI 0
#define SA_LO 5120
#define SB_HI 10240
#define SB_LO 12800
#define STAGE 15360
#define SMEMB (2 * STAGE * 2)   // 61440 bytes

template <bool FUSE, bool OUT16>
__global__ void __launch_bounds__(256) gemm_bf16(const __nv_bfloat16* __restrict__ Ahi,
                                                 const __nv_bfloat16* __restrict__ Alo,
                                                 const __nv_bfloat16* __restrict__ Bthi,
                                                 const __nv_bfloat16* __restrict__ Btlo,
                                                 const float* __restrict__ bias,
                                                 void* __restrict__ Cv,
                                                 const float* __restrict__ asrc,
                                                 const float* __restrict__ adst,
                                                 int M, int K, int Nc) {
    extern __shared__ __nv_bfloat16 smem[];
    uint32_t sbase = smem_u32(smem);

    int tid = threadIdx.x;
    int lane = tid & 31, warp = tid >> 5;
    int wm = warp & 3, wn = warp >> 2;
    int row0 = blockIdx.y * BM, col0 = blockIdx.x * BN;

    int aRow = ((lane & 8) ? 8 : 0) + (lane & 7);
    int aChk = (lane & 16) ? 1 : 0;

    float acc[2][4][4];
    #pragma unroll
    for (int i = 0; i < 2; i++)
        #pragma unroll
        for (int j = 0; j < 4; j++)
            #pragma unroll
            for (int k = 0; k < 4; k++) acc[i][j][k] = 0.f;

    const int ntiles = K / BK;

    auto load_stage = [&](int t, int st) {
        uint32_t sb = sbase + (uint32_t)(st * STAGE * 2);
        int kt = t * BK;
        #pragma unroll
        for (int j = 0; j < 2; j++) {
            int idx = tid + j * 256;
            int r = idx >> 2, ch = idx & 3;
            int gr = row0 + r;
            bool p = gr < M;
            size_t go = (size_t)gr * K + kt + ch * 8;
            uint32_t dof = (uint32_t)((r * RS + ch * 8) * 2);
            cpasync16(sb + SA_HI * 2 + dof, Ahi + go, p);
            cpasync16(sb + SA_LO * 2 + dof, Alo + go, p);
        }
        {
            int r = tid >> 2, ch = tid & 3;
            int gc = col0 + r;
            bool p = gc < Nc;
            size_t go = (size_t)gc * K + kt + ch * 8;
            uint32_t dof = (uint32_t)((r * RS + ch * 8) * 2);
            cpasync16(sb + SB_HI * 2 + dof, Bthi + go, p);
            cpasync16(sb + SB_LO * 2 + dof, Btlo + go, p);
        }
        cp_commit();
    };

    load_stage(0, 0);

    for (int t = 0; t < ntiles; t++) {
        if (t + 1 < ntiles) { load_stage(t + 1, (t + 1) & 1); cp_wait<1>(); }
        else cp_wait<0>();
        __syncthreads();

        uint32_t sb = sbase + (uint32_t)((t & 1) * STAGE * 2);
        uint32_t uAhi = sb + SA_HI * 2, uAlo = sb + SA_LO * 2;
        uint32_t uBhi = sb + SB_HI * 2, uBlo = sb + SB_LO * 2;

        #pragma unroll
        for (int s = 0; s < 2; s++) {
            int kc = 2 * s;
            uint32_t ah0[4], ah1[4], al0[4], al1[4];
            {
                uint32_t base = (uint32_t)(((wm * 32 + aRow) * RS + (kc + aChk) * 8) * 2);
                ldsm4(ah0[0], ah0[1], ah0[2], ah0[3], uAhi + base);
                ldsm4(al0[0], al0[1], al0[2], al0[3], uAlo + base);
                uint32_t base1 = base + (uint32_t)(16 * RS * 2);
                ldsm4(ah1[0], ah1[1], ah1[2], ah1[3], uAhi + base1);
                ldsm4(al1[0], al1[1], al1[2], al1[3], uAlo + base1);
            }
            uint32_t bh_a[4], bh_b[4], bl_a[4], bl_b[4];
            {
                uint32_t base = (uint32_t)(((wn * 32 + lane) * RS + kc * 8) * 2);
                ldsm4(bh_a[0], bh_a[1], bh_a[2], bh_a[3], uBhi + base);
                ldsm4(bl_a[0], bl_a[1], bl_a[2], bl_a[3], uBlo + base);
                uint32_t base1 = base + 16;
                ldsm4(bh_b[0], bh_b[1], bh_b[2], bh_b[3], uBhi + base1);
                ldsm4(bl_b[0], bl_b[1], bl_b[2], bl_b[3], uBlo + base1);
            }
            #pragma unroll
            for (int ni = 0; ni < 4; ni++) {
                uint32_t bh[2] = {bh_a[ni], bh_b[ni]};
                uint32_t bl[2] = {bl_a[ni], bl_b[ni]};
                mma_bf16(acc[0][ni], ah0, bh);
                mma_bf16(acc[0][ni], ah0, bl);
                mma_bf16(acc[0][ni], al0, bh);
                mma_bf16(acc[1][ni], ah1, bh);
                mma_bf16(acc[1][ni], ah1, bl);
                mma_bf16(acc[1][ni], al1, bh);
            }
        }
        __syncthreads();
    }

    // ---- epilogue: C store ----
    int lq = lane >> 2, lr = lane & 3;
    #pragma unroll
    for (int mi = 0; mi < 2; mi++) {
        int r0 = row0 + wm * 32 + mi * 16 + lq;
        #pragma unroll
        for (int ni = 0; ni < 4; ni++) {
            int c = col0 + wn * 32 + ni * 8 + lr * 2;
            if (c < Nc) {
                if (OUT16) {
                    __half* C = (__half*)Cv;
                    if (r0 < M)
                        *(__half2*)(C + (size_t)r0 * Nc + c) =
                            __floats2half2_rn(acc[mi][ni][0], acc[mi][ni][1]);
                    if (r0 + 8 < M)
                        *(__half2*)(C + (size_t)(r0 + 8) * Nc + c) =
                            __floats2half2_rn(acc[mi][ni][2], acc[mi][ni][3]);
                } else {
                    float* C = (float*)Cv;
                    float b0 = bias ? bias[c] : 0.f;
                    float b1 = bias ? bias[c + 1] : 0.f;
                    if (r0 < M)
                        *(float2*)(C + (size_t)r0 * Nc + c) =
                            make_float2(acc[mi][ni][0] + b0, acc[mi][ni][1] + b1);
                    if (r0 + 8 < M)
                        *(float2*)(C + (size_t)(r0 + 8) * Nc + c) =
                            make_float2(acc[mi][ni][2] + b0, acc[mi][ni][3] + b1);
                }
            }
        }
    }

    // ---- fused alpha projections (head = col tile), atomic-free ----
    if (FUSE) {
        float* sred = (float*)smem;          // [0..255] s partials, [256..511] d partials
        int head = col0 >> 6;
        #pragma unroll
        for (int mi = 0; mi < 2; mi++) {
            float s0 = 0.f, s1 = 0.f, d0 = 0.f, d1 = 0.f;
            #pragma unroll
            for (int ni = 0; ni < 4; ni++) {
                int c = col0 + wn * 32 + ni * 8 + lr * 2;
                float ws0 = asrc[c], ws1 = asrc[c + 1];
                float wd0 = adst[c], wd1 = adst[c + 1];
                s0 += acc[mi][ni][0] * ws0 + acc[mi][ni][1] * ws1;
                s1 += acc[mi][ni][2] * ws0 + acc[mi][ni][3] * ws1;
                d0 += acc[mi][ni][0] * wd0 + acc[mi][ni][1] * wd1;
                d1 += acc[mi][ni][2] * wd0 + acc[mi][ni][3] * wd1;
            }
            #pragma unroll
            for (int o = 1; o <= 2; o <<= 1) {
                s0 += __shfl_xor_sync(0xffffffffu, s0, o);
                s1 += __shfl_xor_sync(0xffffffffu, s1, o);
                d0 += __shfl_xor_sync(0xffffffffu, d0, o);
                d1 += __shfl_xor_sync(0xffffffffu, d1, o);
            }
            if (lr == 0) {
                int rl0 = wm * 32 + mi * 16 + lq;
                sred[rl0 * 2 + wn] = s0;
                sred[(rl0 + 8) * 2 + wn] = s1;
                sred[256 + rl0 * 2 + wn] = d0;
                sred[256 + (rl0 + 8) * 2 + wn] = d1;
            }
        }
        __syncthreads();
        if (tid < 128) {
            int gr = row0 + tid;
            if (gr < M) {
                g_as[gr * 3 + head] = sred[tid * 2] + sred[tid * 2 + 1];
                g_ad[gr * 3 + head] = sred[256 + tid * 2] + sred[256 + tid * 2 + 1];
            }
        }
    }
}

// ---------------- GAT aggregation: warp/node, fp16 gather, no max pass ----------------
__global__ void agg_kernel(const __half* __restrict__ h, const float* __restrict__ bias,
                           __nv_bfloat16* __restrict__ ohi, __nv_bfloat16* __restrict__ olo) {
    int gw = (blockIdx.x * blockDim.x + threadIdx.x) >> 5;
    int lane = threadIdx.x & 31;
    if (gw >= NN) return;
    int beg = g_rowptr[gw], end = g_rowptr[gw + 1];
    float ad0 = g_ad[gw * 3 + 0], ad1 = g_ad[gw * 3 + 1], ad2 = g_ad[gw * 3 + 2];

    // denominators (softmax shift-invariant; scores bounded ~|8| -> exp safe in fp32)
    float d0 = 0.f, d1 = 0.f, d2 = 0.f;
    for (int i = beg + lane; i < end; i += 32) {
        int s = g_srcs[i];
        d0 += __expf(lrelu(g_as[s * 3 + 0] + ad0));
        d1 += __expf(lrelu(g_as[s * 3 + 1] + ad1));
        d2 += __expf(lrelu(g_as[s * 3 + 2] + ad2));
    }
    d0 = wsum(d0); d1 = wsum(d1); d2 = wsum(d2);
    float i0 = 1.f / (d0 + 1e-16f), i1 = 1.f / (d1 + 1e-16f), i2 = 1.f / (d2 + 1e-16f);

    // weighted gather: each lane owns cols {2*lane, 2*lane+1} of each head
    float2 a0 = make_float2(0.f, 0.f), a1 = a0, a2 = a0;
    for (int i = beg; i < end; i++) {
        int s = g_srcs[i];
        float w0 = __expf(lrelu(g_as[s * 3 + 0] + ad0)) * i0;
        float w1 = __expf(lrelu(g_as[s * 3 + 1] + ad1)) * i1;
        float w2 = __expf(lrelu(g_as[s * 3 + 2] + ad2)) * i2;
        const __half2* hs = (const __half2*)(h + (size_t)s * HC);
        float2 f0 = __half22float2(hs[lane]);
        float2 f1 = __half22float2(hs[32 + lane]);
        float2 f2 = __half22float2(hs[64 + lane]);
        a0.x += f0.x * w0; a0.y += f0.y * w0;
        a1.x += f1.x * w1; a1.y += f1.y * w1;
        a2.x += f2.x * w2; a2.y += f2.y * w2;
    }
    float2 av[3] = {a0, a1, a2};
    #pragma unroll
    for (int q = 0; q < 3; q++) {
        int c = q * 64 + 2 * lane;
        float v0 = elu_f(av[q].x + bias[c]);
        float v1 = elu_f(av[q].y + bias[c + 1]);
        __nv_bfloat16 h0 = __float2bfloat16(v0), h1 = __float2bfloat16(v1);
        __nv_bfloat16 l0 = __float2bfloat16(v0 - __bfloat162float(h0));
        __nv_bfloat16 l1 = __float2bfloat16(v1 - __bfloat162float(h1));
        size_t idx = (size_t)gw * HC + c;
        __nv_bfloat162 hp; hp.x = h0; hp.y = h1;
        __nv_bfloat162 lp; lp.x = l0; lp.y = l1;
        *(__nv_bfloat162*)(ohi + idx) = hp;
        *(__nv_bfloat162*)(olo + idx) = lp;
    }
}

// ---------------- launch ----------------
extern "C" void kernel_launch(void* const* d_in, const int* in_sizes, int n_in,
                              void* d_out, int out_size) {
    const float* x     = (const float*)d_in[0];
    const int*   ei    = (const int*)  d_in[1];
    const float* W1    = (const float*)d_in[2];
    const float* asrc1 = (const float*)d_in[3];
    const float* adst1 = (const float*)d_in[4];
    const float* b1    = (const float*)d_in[5];
    const float* W2    = (const float*)d_in[6];
    const float* asrc2 = (const float*)d_in[7];
    const float* adst2 = (const float*)d_in[8];
    const float* b2    = (const float*)d_in[9];
    const float* Wf1   = (const float*)d_in[10];
    const float* bf1   = (const float*)d_in[11];
    const float* Wf2   = (const float*)d_in[12];
    const float* bf2   = (const float*)d_in[13];
    float* out = (float*)d_out;

    float *bf;
    __half* h;
    __nv_bfloat16 *xhi, *xlo, *hxhi, *hxlo, *w1thi, *w1tlo, *w2thi, *w2tlo, *wfthi, *wftlo;
    cudaGetSymbolAddress((void**)&h,     g_h);
    cudaGetSymbolAddress((void**)&bf,    g_bf);
    cudaGetSymbolAddress((void**)&xhi,   g_xhi);
    cudaGetSymbolAddress((void**)&xlo,   g_xlo);
    cudaGetSymbolAddress((void**)&hxhi,  g_hxhi);
    cudaGetSymbolAddress((void**)&hxlo,  g_hxlo);
    cudaGetSymbolAddress((void**)&w1thi, g_w1thi);
    cudaGetSymbolAddress((void**)&w1tlo, g_w1tlo);
    cudaGetSymbolAddress((void**)&w2thi, g_w2thi);
    cudaGetSymbolAddress((void**)&w2tlo, g_w2tlo);
    cudaGetSymbolAddress((void**)&wfthi, g_wfthi);
    cudaGetSymbolAddress((void**)&wftlo, g_wftlo);

    const int* srcp = ei;
    const int* dstp = ei + EE;

    cudaFuncSetAttribute(gemm_bf16<true, true>,   cudaFuncAttributeMaxDynamicSharedMemorySize, SMEMB);
    cudaFuncSetAttribute(gemm_bf16<false, false>, cudaFuncAttributeMaxDynamicSharedMemorySize, SMEMB);

    int warpBlocks = (NN * 32 + 255) / 256;
    int gy = (NN + BM - 1) / BM;

    // prep first so gemm lands in the ncu capture slot
    split_kernel<<<(NN * INC / 4 + 255) / 256, 256>>>(x, xhi, xlo, NN * INC / 4);
    wsplit_kernel<<<(INC * HC + 255) / 256, 256>>>(W1, w1thi, w1tlo, INC, HC);
    wsplit_kernel<<<(HC * HC + 255) / 256, 256>>>(W2, w2thi, w2tlo, HC, HC);

    // layer-1 GEMM (+fused alpha)
    gemm_bf16<true, true><<<dim3(HC / BN, gy), 256, SMEMB>>>(xhi, xlo, w1thi, w1tlo, nullptr, h,
                                                             asrc1, adst1, NN, INC, HC);

    // CSR build (overlapping position; sequential stream anyway)
    zero_kernel<<<(NN + 255) / 256, 256>>>();
    count_kernel<<<(ET + 255) / 256, 256>>>(dstp);
    scan_kernel<<<1, 1024>>>();
    bucket_kernel<<<(ET + 255) / 256, 256>>>(srcp, dstp);
    fuse_mlp_kernel<<<(HC * OUTC + OUTC + 255) / 256, 256>>>(Wf1, bf1, Wf2, bf2);

    agg_kernel<<<warpBlocks, 256>>>(h, b1, hxhi, hxlo);

    // layer 2
    gemm_bf16<true, true><<<dim3(HC / BN, gy), 256, SMEMB>>>(hxhi, hxlo, w2thi, w2tlo, nullptr, h,
                                                             asrc2, adst2, NN, HC, HC);
    agg_kernel<<<warpBlocks, 256>>>(h, b2, hxhi, hxlo);

    // fused MLP head
    gemm_bf16<false, false><<<dim3(1, gy), 256, SMEMB>>>(hxhi, hxlo, wfthi, wftlo, bf, out,
                                                         nullptr, nullptr, NN, HC, OUTC);
}

// round 7
// speedup vs baseline: 2.4563x; 1.1572x over previous
#include <cuda_runtime.h>
#include <cuda_bf16.h>
#include <cuda_fp16.h>
#include <math.h>
#include <stdint.h>

#define NN   50000
#define EE   800000
#define ET   (EE + NN)
#define INC  128
#define HC   192
#define OUTC 32

// ---------------- scratch ----------------
__device__ __half g_h[NN * HC];                       // fp16 h table (agg gather)
__device__ float4 g_ew[ET];                           // per-edge exp weights (x,y,z used)
__device__ __nv_bfloat16 g_xhi[NN * INC], g_xlo[NN * INC];
__device__ __nv_bfloat16 g_hxhi[NN * HC], g_hxlo[NN * HC];
__device__ __nv_bfloat16 g_w1thi[HC * INC], g_w1tlo[HC * INC];
__device__ __nv_bfloat16 g_w2thi[HC * HC],  g_w2tlo[HC * HC];
__device__ __nv_bfloat16 g_wfthi[OUTC * HC], g_wftlo[OUTC * HC];
__device__ float g_bf[OUTC];
__device__ float g_as[NN * 3];
__device__ float g_ad[NN * 3];
__device__ int   g_deg[NN];
__device__ int   g_ctr[NN];
__device__ int   g_rowptr[NN + 1];
__device__ int   g_srcs[ET];

// ---------------- helpers ----------------
__device__ __forceinline__ float lrelu(float v) { return v > 0.f ? v : 0.2f * v; }
__device__ __forceinline__ float elu_f(float v) { return v > 0.f ? v : expm1f(v); }
__device__ __forceinline__ float wsum(float v) {
    #pragma unroll
    for (int o = 16; o > 0; o >>= 1) v += __shfl_xor_sync(0xffffffffu, v, o);
    return v;
}
__device__ __forceinline__ uint32_t smem_u32(const void* p) {
    uint32_t a;
    asm("{ .reg .u64 t; cvta.to.shared.u64 t, %1; cvt.u32.u64 %0, t; }" : "=r"(a) : "l"(p));
    return a;
}
__device__ __forceinline__ void ldsm4(uint32_t& r0, uint32_t& r1, uint32_t& r2, uint32_t& r3, uint32_t a) {
    asm volatile("ldmatrix.sync.aligned.m8n8.x4.shared.b16 {%0,%1,%2,%3}, [%4];"
                 : "=r"(r0), "=r"(r1), "=r"(r2), "=r"(r3) : "r"(a));
}
__device__ __forceinline__ void mma_bf16(float* c, const uint32_t* a, const uint32_t* b) {
    asm volatile(
        "mma.sync.aligned.m16n8k16.row.col.f32.bf16.bf16.f32 "
        "{%0,%1,%2,%3}, {%4,%5,%6,%7}, {%8,%9}, {%0,%1,%2,%3};"
        : "+f"(c[0]), "+f"(c[1]), "+f"(c[2]), "+f"(c[3])
        : "r"(a[0]), "r"(a[1]), "r"(a[2]), "r"(a[3]), "r"(b[0]), "r"(b[1]));
}
__device__ __forceinline__ void cpasync16(uint32_t dst, const void* src, bool pred) {
    int sz = pred ? 16 : 0;
    asm volatile("cp.async.cg.shared.global [%0], [%1], 16, %2;"
                 :: "r"(dst), "l"(src), "r"(sz) : "memory");
}
__device__ __forceinline__ void cp_commit() { asm volatile("cp.async.commit_group;" ::: "memory"); }
template <int N>
__device__ __forceinline__ void cp_wait() { asm volatile("cp.async.wait_group %0;" :: "n"(N) : "memory"); }

// ---------------- CSR build ----------------
__global__ void zero_kernel() {
    int i = blockIdx.x * blockDim.x + threadIdx.x;
    if (i < NN) { g_deg[i] = 0; g_ctr[i] = 0; }
}
__global__ void count_kernel(const int* __restrict__ dst) {
    int i = blockIdx.x * blockDim.x + threadIdx.x;
    if (i >= ET) return;
    int d = (i < EE) ? dst[i] : (i - EE);
    atomicAdd(&g_deg[d], 1);
}
__global__ void scan_kernel() {
    __shared__ int part[1024];
    const int per = (NN + 1023) / 1024;
    int t = threadIdx.x;
    int start = t * per, end = min(start + per, NN);
    int s = 0;
    for (int i = start; i < end; i++) s += g_deg[i];
    part[t] = s;
    __syncthreads();
    for (int off = 1; off < 1024; off <<= 1) {
        int v = (t >= off) ? part[t - off] : 0;
        __syncthreads();
        part[t] += v;
        __syncthreads();
    }
    int run = part[t] - s;
    for (int i = start; i < end; i++) { g_rowptr[i] = run; run += g_deg[i]; }
    if (t == 1023) g_rowptr[NN] = part[1023];
}
__global__ void bucket_kernel(const int* __restrict__ src, const int* __restrict__ dst) {
    int i = blockIdx.x * blockDim.x + threadIdx.x;
    if (i >= ET) return;
    int s, d;
    if (i < EE) { s = src[i]; d = dst[i]; } else { s = i - EE; d = s; }
    int pos = atomicAdd(&g_ctr[d], 1);
    g_srcs[g_rowptr[d] + pos] = s;
}

// ---------------- operand prep ----------------
__global__ void split_kernel(const float* __restrict__ in, __nv_bfloat16* __restrict__ hi,
                             __nv_bfloat16* __restrict__ lo, int n4) {
    int i = blockIdx.x * blockDim.x + threadIdx.x;
    if (i >= n4) return;
    float4 v = ((const float4*)in)[i];
    float vv[4] = {v.x, v.y, v.z, v.w};
    __nv_bfloat16 h[4], l[4];
    #pragma unroll
    for (int j = 0; j < 4; j++) {
        h[j] = __float2bfloat16(vv[j]);
        l[j] = __float2bfloat16(vv[j] - __bfloat162float(h[j]));
    }
    ((ushort4*)hi)[i] = make_ushort4(*(uint16_t*)&h[0], *(uint16_t*)&h[1], *(uint16_t*)&h[2], *(uint16_t*)&h[3]);
    ((ushort4*)lo)[i] = make_ushort4(*(uint16_t*)&l[0], *(uint16_t*)&l[1], *(uint16_t*)&l[2], *(uint16_t*)&l[3]);
}
__global__ void wsplit_kernel(const float* __restrict__ W, __nv_bfloat16* __restrict__ thi,
                              __nv_bfloat16* __restrict__ tlo, int K, int Nc) {
    int i = blockIdx.x * blockDim.x + threadIdx.x;
    if (i >= K * Nc) return;
    int k = i / Nc, c = i - k * Nc;
    float v = W[i];
    __nv_bfloat16 h = __float2bfloat16(v);
    thi[c * K + k] = h;
    tlo[c * K + k] = __float2bfloat16(v - __bfloat162float(h));
}
__global__ void fuse_mlp_kernel(const float* __restrict__ Wf1, const float* __restrict__ bf1,
                                const float* __restrict__ Wf2, const float* __restrict__ bf2) {
    int i = blockIdx.x * blockDim.x + threadIdx.x;
    if (i < HC * OUTC) {
        int r = i >> 5, c = i & 31;
        float s = 0.f;
        #pragma unroll 8
        for (int j = 0; j < 64; j++) s += Wf1[r * 64 + j] * Wf2[j * OUTC + c];
        __nv_bfloat16 h = __float2bfloat16(s);
        g_wfthi[c * HC + r] = h;
        g_wftlo[c * HC + r] = __float2bfloat16(s - __bfloat162float(h));
    } else if (i < HC * OUTC + OUTC) {
        int c = i - HC * OUTC;
        float s = bf2[c];
        for (int j = 0; j < 64; j++) s += bf1[j] * Wf2[j * OUTC + c];
        g_bf[c] = s;
    }
}

// ---------------- bf16-split tensor-core GEMM, double-buffered cp.async ----------------
#define BM 128
#define BN 64
#define BK 32
#define RS 40
#define SA_HI 0
#define SA_LO 5120
#define SB_HI 10240
#define SB_LO 12800
#define STAGE 15360
#define SMEMB (2 * STAGE * 2)   // 61440 bytes

template <bool FUSE, bool OUT16>
__global__ void __launch_bounds__(256) gemm_bf16(const __nv_bfloat16* __restrict__ Ahi,
                                                 const __nv_bfloat16* __restrict__ Alo,
                                                 const __nv_bfloat16* __restrict__ Bthi,
                                                 const __nv_bfloat16* __restrict__ Btlo,
                                                 const float* __restrict__ bias,
                                                 void* __restrict__ Cv,
                                                 const float* __restrict__ asrc,
                                                 const float* __restrict__ adst,
                                                 int M, int K, int Nc) {
    extern __shared__ __nv_bfloat16 smem[];
    uint32_t sbase = smem_u32(smem);

    int tid = threadIdx.x;
    int lane = tid & 31, warp = tid >> 5;
    int wm = warp & 3, wn = warp >> 2;
    int row0 = blockIdx.y * BM, col0 = blockIdx.x * BN;

    int aRow = ((lane & 8) ? 8 : 0) + (lane & 7);
    int aChk = (lane & 16) ? 1 : 0;

    float acc[2][4][4];
    #pragma unroll
    for (int i = 0; i < 2; i++)
        #pragma unroll
        for (int j = 0; j < 4; j++)
            #pragma unroll
            for (int k = 0; k < 4; k++) acc[i][j][k] = 0.f;

    const int ntiles = K / BK;

    auto load_stage = [&](int t, int st) {
        uint32_t sb = sbase + (uint32_t)(st * STAGE * 2);
        int kt = t * BK;
        #pragma unroll
        for (int j = 0; j < 2; j++) {
            int idx = tid + j * 256;
            int r = idx >> 2, ch = idx & 3;
            int gr = row0 + r;
            bool p = gr < M;
            size_t go = (size_t)gr * K + kt + ch * 8;
            uint32_t dof = (uint32_t)((r * RS + ch * 8) * 2);
            cpasync16(sb + SA_HI * 2 + dof, Ahi + go, p);
            cpasync16(sb + SA_LO * 2 + dof, Alo + go, p);
        }
        {
            int r = tid >> 2, ch = tid & 3;
            int gc = col0 + r;
            bool p = gc < Nc;
            size_t go = (size_t)gc * K + kt + ch * 8;
            uint32_t dof = (uint32_t)((r * RS + ch * 8) * 2);
            cpasync16(sb + SB_HI * 2 + dof, Bthi + go, p);
            cpasync16(sb + SB_LO * 2 + dof, Btlo + go, p);
        }
        cp_commit();
    };

    load_stage(0, 0);

    for (int t = 0; t < ntiles; t++) {
        if (t + 1 < ntiles) { load_stage(t + 1, (t + 1) & 1); cp_wait<1>(); }
        else cp_wait<0>();
        __syncthreads();

        uint32_t sb = sbase + (uint32_t)((t & 1) * STAGE * 2);
        uint32_t uAhi = sb + SA_HI * 2, uAlo = sb + SA_LO * 2;
        uint32_t uBhi = sb + SB_HI * 2, uBlo = sb + SB_LO * 2;

        #pragma unroll
        for (int s = 0; s < 2; s++) {
            int kc = 2 * s;
            uint32_t ah0[4], ah1[4], al0[4], al1[4];
            {
                uint32_t base = (uint32_t)(((wm * 32 + aRow) * RS + (kc + aChk) * 8) * 2);
                ldsm4(ah0[0], ah0[1], ah0[2], ah0[3], uAhi + base);
                ldsm4(al0[0], al0[1], al0[2], al0[3], uAlo + base);
                uint32_t base1 = base + (uint32_t)(16 * RS * 2);
                ldsm4(ah1[0], ah1[1], ah1[2], ah1[3], uAhi + base1);
                ldsm4(al1[0], al1[1], al1[2], al1[3], uAlo + base1);
            }
            uint32_t bh_a[4], bh_b[4], bl_a[4], bl_b[4];
            {
                uint32_t base = (uint32_t)(((wn * 32 + lane) * RS + kc * 8) * 2);
                ldsm4(bh_a[0], bh_a[1], bh_a[2], bh_a[3], uBhi + base);
                ldsm4(bl_a[0], bl_a[1], bl_a[2], bl_a[3], uBlo + base);
                uint32_t base1 = base + 16;
                ldsm4(bh_b[0], bh_b[1], bh_b[2], bh_b[3], uBhi + base1);
                ldsm4(bl_b[0], bl_b[1], bl_b[2], bl_b[3], uBlo + base1);
            }
            #pragma unroll
            for (int ni = 0; ni < 4; ni++) {
                uint32_t bh[2] = {bh_a[ni], bh_b[ni]};
                uint32_t bl[2] = {bl_a[ni], bl_b[ni]};
                mma_bf16(acc[0][ni], ah0, bh);
                mma_bf16(acc[0][ni], ah0, bl);
                mma_bf16(acc[0][ni], al0, bh);
                mma_bf16(acc[1][ni], ah1, bh);
                mma_bf16(acc[1][ni], ah1, bl);
                mma_bf16(acc[1][ni], al1, bh);
            }
        }
        __syncthreads();
    }

    // ---- epilogue: C store ----
    int lq = lane >> 2, lr = lane & 3;
    #pragma unroll
    for (int mi = 0; mi < 2; mi++) {
        int r0 = row0 + wm * 32 + mi * 16 + lq;
        #pragma unroll
        for (int ni = 0; ni < 4; ni++) {
            int c = col0 + wn * 32 + ni * 8 + lr * 2;
            if (c < Nc) {
                if (OUT16) {
                    __half* C = (__half*)Cv;
                    if (r0 < M)
                        *(__half2*)(C + (size_t)r0 * Nc + c) =
                            __floats2half2_rn(acc[mi][ni][0], acc[mi][ni][1]);
                    if (r0 + 8 < M)
                        *(__half2*)(C + (size_t)(r0 + 8) * Nc + c) =
                            __floats2half2_rn(acc[mi][ni][2], acc[mi][ni][3]);
                } else {
                    float* C = (float*)Cv;
                    float b0 = bias ? bias[c] : 0.f;
                    float b1 = bias ? bias[c + 1] : 0.f;
                    if (r0 < M)
                        *(float2*)(C + (size_t)r0 * Nc + c) =
                            make_float2(acc[mi][ni][0] + b0, acc[mi][ni][1] + b1);
                    if (r0 + 8 < M)
                        *(float2*)(C + (size_t)(r0 + 8) * Nc + c) =
                            make_float2(acc[mi][ni][2] + b0, acc[mi][ni][3] + b1);
                }
            }
        }
    }

    // ---- fused alpha projections (head = col tile), atomic-free ----
    if (FUSE) {
        float* sred = (float*)smem;
        int head = col0 >> 6;
        #pragma unroll
        for (int mi = 0; mi < 2; mi++) {
            float s0 = 0.f, s1 = 0.f, d0 = 0.f, d1 = 0.f;
            #pragma unroll
            for (int ni = 0; ni < 4; ni++) {
                int c = col0 + wn * 32 + ni * 8 + lr * 2;
                float ws0 = asrc[c], ws1 = asrc[c + 1];
                float wd0 = adst[c], wd1 = adst[c + 1];
                s0 += acc[mi][ni][0] * ws0 + acc[mi][ni][1] * ws1;
                s1 += acc[mi][ni][2] * ws0 + acc[mi][ni][3] * ws1;
                d0 += acc[mi][ni][0] * wd0 + acc[mi][ni][1] * wd1;
                d1 += acc[mi][ni][2] * wd0 + acc[mi][ni][3] * wd1;
            }
            #pragma unroll
            for (int o = 1; o <= 2; o <<= 1) {
                s0 += __shfl_xor_sync(0xffffffffu, s0, o);
                s1 += __shfl_xor_sync(0xffffffffu, s1, o);
                d0 += __shfl_xor_sync(0xffffffffu, d0, o);
                d1 += __shfl_xor_sync(0xffffffffu, d1, o);
            }
            if (lr == 0) {
                int rl0 = wm * 32 + mi * 16 + lq;
                sred[rl0 * 2 + wn] = s0;
                sred[(rl0 + 8) * 2 + wn] = s1;
                sred[256 + rl0 * 2 + wn] = d0;
                sred[256 + (rl0 + 8) * 2 + wn] = d1;
            }
        }
        __syncthreads();
        if (tid < 128) {
            int gr = row0 + tid;
            if (gr < M) {
                g_as[gr * 3 + head] = sred[tid * 2] + sred[tid * 2 + 1];
                g_ad[gr * 3 + head] = sred[256 + tid * 2] + sred[256 + tid * 2 + 1];
            }
        }
    }
}

// ---------------- GAT aggregation: warp/node, per-edge exp computed ONCE ----------------
__global__ void agg_kernel(const __half* __restrict__ h, const float* __restrict__ bias,
                           __nv_bfloat16* __restrict__ ohi, __nv_bfloat16* __restrict__ olo) {
    int gw = (blockIdx.x * blockDim.x + threadIdx.x) >> 5;
    int lane = threadIdx.x & 31;
    if (gw >= NN) return;
    int beg = g_rowptr[gw], end = g_rowptr[gw + 1];
    float ad0 = g_ad[gw * 3 + 0], ad1 = g_ad[gw * 3 + 1], ad2 = g_ad[gw * 3 + 2];

    // pass 1: per-edge exp weights (computed once, lane-parallel) + denominators
    float d0 = 0.f, d1 = 0.f, d2 = 0.f;
    for (int i = beg + lane; i < end; i += 32) {
        int s = g_srcs[i];
        float e0 = __expf(lrelu(g_as[s * 3 + 0] + ad0));
        float e1 = __expf(lrelu(g_as[s * 3 + 1] + ad1));
        float e2 = __expf(lrelu(g_as[s * 3 + 2] + ad2));
        g_ew[i] = make_float4(e0, e1, e2, 0.f);
        d0 += e0; d1 += e1; d2 += e2;
    }
    d0 = wsum(d0); d1 = wsum(d1); d2 = wsum(d2);
    float i0 = 1.f / (d0 + 1e-16f), i1 = 1.f / (d1 + 1e-16f), i2 = 1.f / (d2 + 1e-16f);

    // pass 2: weighted gather; weights come from g_ew (broadcast ldg.128, no MUFU)
    float2 a0 = make_float2(0.f, 0.f), a1 = a0, a2 = a0;
    #pragma unroll 4
    for (int i = beg; i < end; i++) {
        int s = g_srcs[i];
        float4 w = g_ew[i];
        const __half2* hs = (const __half2*)(h + (size_t)s * HC);
        float2 f0 = __half22float2(hs[lane]);
        float2 f1 = __half22float2(hs[32 + lane]);
        float2 f2 = __half22float2(hs[64 + lane]);
        a0.x += f0.x * w.x; a0.y += f0.y * w.x;
        a1.x += f1.x * w.y; a1.y += f1.y * w.y;
        a2.x += f2.x * w.z; a2.y += f2.y * w.z;
    }
    a0.x *= i0; a0.y *= i0;
    a1.x *= i1; a1.y *= i1;
    a2.x *= i2; a2.y *= i2;

    float2 av[3] = {a0, a1, a2};
    #pragma unroll
    for (int q = 0; q < 3; q++) {
        int c = q * 64 + 2 * lane;
        float v0 = elu_f(av[q].x + bias[c]);
        float v1 = elu_f(av[q].y + bias[c + 1]);
        __nv_bfloat16 h0 = __float2bfloat16(v0), h1 = __float2bfloat16(v1);
        __nv_bfloat16 l0 = __float2bfloat16(v0 - __bfloat162float(h0));
        __nv_bfloat16 l1 = __float2bfloat16(v1 - __bfloat162float(h1));
        size_t idx = (size_t)gw * HC + c;
        __nv_bfloat162 hp; hp.x = h0; hp.y = h1;
        __nv_bfloat162 lp; lp.x = l0; lp.y = l1;
        *(__nv_bfloat162*)(ohi + idx) = hp;
        *(__nv_bfloat162*)(olo + idx) = lp;
    }
}

// ---------------- launch ----------------
extern "C" void kernel_launch(void* const* d_in, const int* in_sizes, int n_in,
                              void* d_out, int out_size) {
    const float* x     = (const float*)d_in[0];
    const int*   ei    = (const int*)  d_in[1];
    const float* W1    = (const float*)d_in[2];
    const float* asrc1 = (const float*)d_in[3];
    const float* adst1 = (const float*)d_in[4];
    const float* b1    = (const float*)d_in[5];
    const float* W2    = (const float*)d_in[6];
    const float* asrc2 = (const float*)d_in[7];
    const float* adst2 = (const float*)d_in[8];
    const float* b2    = (const float*)d_in[9];
    const float* Wf1   = (const float*)d_in[10];
    const float* bf1   = (const float*)d_in[11];
    const float* Wf2   = (const float*)d_in[12];
    const float* bf2   = (const float*)d_in[13];
    float* out = (float*)d_out;

    float *bf;
    __half* h;
    __nv_bfloat16 *xhi, *xlo, *hxhi, *hxlo, *w1thi, *w1tlo, *w2thi, *w2tlo, *wfthi, *wftlo;
    cudaGetSymbolAddress((void**)&h,     g_h);
    cudaGetSymbolAddress((void**)&bf,    g_bf);
    cudaGetSymbolAddress((void**)&xhi,   g_xhi);
    cudaGetSymbolAddress((void**)&xlo,   g_xlo);
    cudaGetSymbolAddress((void**)&hxhi,  g_hxhi);
    cudaGetSymbolAddress((void**)&hxlo,  g_hxlo);
    cudaGetSymbolAddress((void**)&w1thi, g_w1thi);
    cudaGetSymbolAddress((void**)&w1tlo, g_w1tlo);
    cudaGetSymbolAddress((void**)&w2thi, g_w2thi);
    cudaGetSymbolAddress((void**)&w2tlo, g_w2tlo);
    cudaGetSymbolAddress((void**)&wfthi, g_wfthi);
    cudaGetSymbolAddress((void**)&wftlo, g_wftlo);

    const int* srcp = ei;
    const int* dstp = ei + EE;

    cudaFuncSetAttribute(gemm_bf16<true, true>,   cudaFuncAttributeMaxDynamicSharedMemorySize, SMEMB);
    cudaFuncSetAttribute(gemm_bf16<false, false>, cudaFuncAttributeMaxDynamicSharedMemorySize, SMEMB);

    int warpBlocks = (NN * 32 + 255) / 256;
    int gy = (NN + BM - 1) / BM;

    split_kernel<<<(NN * INC / 4 + 255) / 256, 256>>>(x, xhi, xlo, NN * INC / 4);
    wsplit_kernel<<<(INC * HC + 255) / 256, 256>>>(W1, w1thi, w1tlo, INC, HC);
    wsplit_kernel<<<(HC * HC + 255) / 256, 256>>>(W2, w2thi, w2tlo, HC, HC);

    // layer-1 GEMM (+fused alpha)
    gemm_bf16<true, true><<<dim3(HC / BN, gy), 256, SMEMB>>>(xhi, xlo, w1thi, w1tlo, nullptr, h,
                                                             asrc1, adst1, NN, INC, HC);

    // CSR build
    zero_kernel<<<(NN + 255) / 256, 256>>>();
    count_kernel<<<(ET + 255) / 256, 256>>>(dstp);
    scan_kernel<<<1, 1024>>>();
    bucket_kernel<<<(ET + 255) / 256, 256>>>(srcp, dstp);
    fuse_mlp_kernel<<<(HC * OUTC + OUTC + 255) / 256, 256>>>(Wf1, bf1, Wf2, bf2);

    agg_kernel<<<warpBlocks, 256>>>(h, b1, hxhi, hxlo);

    // layer 2
    gemm_bf16<true, true><<<dim3(HC / BN, gy), 256, SMEMB>>>(hxhi, hxlo, w2thi, w2tlo, nullptr, h,
                                                             asrc2, adst2, NN, HC, HC);
    agg_kernel<<<warpBlocks, 256>>>(h, b2, hxhi, hxlo);

    // fused MLP head
    gemm_bf16<false, false><<<dim3(1, gy), 256, SMEMB>>>(hxhi, hxlo, wfthi, wftlo, bf, out,
                                                         nullptr, nullptr, NN, HC, OUTC);
}

// round 8
// speedup vs baseline: 2.8598x; 1.1643x over previous
#include <cuda_runtime.h>
#include <cuda_bf16.h>
#include <cuda_fp16.h>
#include <math.h>
#include <stdint.h>

#define NN   50000
#define EE   800000
#define ET   (EE + NN)
#define INC  128
#define HC   192
#define OUTC 32

// ---------------- scratch ----------------
__device__ __half g_h[NN * HC];                       // fp16 h table (agg gather)
__device__ float4 g_ew[ET];                           // per-edge exp weights (x,y,z used)
__device__ __nv_bfloat16 g_xhi[NN * INC], g_xlo[NN * INC];
__device__ __nv_bfloat16 g_hxhi[NN * HC], g_hxlo[NN * HC];
__device__ __nv_bfloat16 g_w1thi[HC * INC], g_w1tlo[HC * INC];
__device__ __nv_bfloat16 g_w2thi[HC * HC],  g_w2tlo[HC * HC];
__device__ __nv_bfloat16 g_wfthi[OUTC * HC], g_wftlo[OUTC * HC];
__device__ float g_bf[OUTC];
__device__ float g_as[NN * 3];
__device__ float g_ad[NN * 3];
__device__ int   g_deg[NN];
__device__ int   g_ctr[NN];
__device__ int   g_rowptr[NN + 1];
__device__ int   g_srcs[ET];

// ---------------- helpers ----------------
__device__ __forceinline__ float lrelu(float v) { return v > 0.f ? v : 0.2f * v; }
__device__ __forceinline__ float elu_f(float v) { return v > 0.f ? v : expm1f(v); }
__device__ __forceinline__ float wsum(float v) {
    #pragma unroll
    for (int o = 16; o > 0; o >>= 1) v += __shfl_xor_sync(0xffffffffu, v, o);
    return v;
}
__device__ __forceinline__ uint32_t smem_u32(const void* p) {
    uint32_t a;
    asm("{ .reg .u64 t; cvta.to.shared.u64 t, %1; cvt.u32.u64 %0, t; }" : "=r"(a) : "l"(p));
    return a;
}
__device__ __forceinline__ void ldsm4(uint32_t& r0, uint32_t& r1, uint32_t& r2, uint32_t& r3, uint32_t a) {
    asm volatile("ldmatrix.sync.aligned.m8n8.x4.shared.b16 {%0,%1,%2,%3}, [%4];"
                 : "=r"(r0), "=r"(r1), "=r"(r2), "=r"(r3) : "r"(a));
}
__device__ __forceinline__ void mma_bf16(float* c, const uint32_t* a, const uint32_t* b) {
    asm volatile(
        "mma.sync.aligned.m16n8k16.row.col.f32.bf16.bf16.f32 "
        "{%0,%1,%2,%3}, {%4,%5,%6,%7}, {%8,%9}, {%0,%1,%2,%3};"
        : "+f"(c[0]), "+f"(c[1]), "+f"(c[2]), "+f"(c[3])
        : "r"(a[0]), "r"(a[1]), "r"(a[2]), "r"(a[3]), "r"(b[0]), "r"(b[1]));
}
__device__ __forceinline__ void cpasync16(uint32_t dst, const void* src, bool pred) {
    int sz = pred ? 16 : 0;
    asm volatile("cp.async.cg.shared.global [%0], [%1], 16, %2;"
                 :: "r"(dst), "l"(src), "r"(sz) : "memory");
}
__device__ __forceinline__ void cp_commit() { asm volatile("cp.async.commit_group;" ::: "memory"); }
template <int N>
__device__ __forceinline__ void cp_wait() { asm volatile("cp.async.wait_group %0;" :: "n"(N) : "memory"); }

// ---------------- CSR build ----------------
__global__ void zero_kernel() {
    int i = blockIdx.x * blockDim.x + threadIdx.x;
    if (i < NN) { g_deg[i] = 0; g_ctr[i] = 0; }
}
__global__ void count_kernel(const int* __restrict__ dst) {
    int i = blockIdx.x * blockDim.x + threadIdx.x;
    if (i >= ET) return;
    int d = (i < EE) ? dst[i] : (i - EE);
    atomicAdd(&g_deg[d], 1);
}
__global__ void scan_kernel() {
    __shared__ int part[1024];
    const int per = (NN + 1023) / 1024;
    int t = threadIdx.x;
    int start = t * per, end = min(start + per, NN);
    int s = 0;
    for (int i = start; i < end; i++) s += g_deg[i];
    part[t] = s;
    __syncthreads();
    for (int off = 1; off < 1024; off <<= 1) {
        int v = (t >= off) ? part[t - off] : 0;
        __syncthreads();
        part[t] += v;
        __syncthreads();
    }
    int run = part[t] - s;
    for (int i = start; i < end; i++) { g_rowptr[i] = run; run += g_deg[i]; }
    if (t == 1023) g_rowptr[NN] = part[1023];
}
__global__ void bucket_kernel(const int* __restrict__ src, const int* __restrict__ dst) {
    int i = blockIdx.x * blockDim.x + threadIdx.x;
    if (i >= ET) return;
    int s, d;
    if (i < EE) { s = src[i]; d = dst[i]; } else { s = i - EE; d = s; }
    int pos = atomicAdd(&g_ctr[d], 1);
    g_srcs[g_rowptr[d] + pos] = s;
}

// ---------------- operand prep ----------------
__global__ void split_kernel(const float* __restrict__ in, __nv_bfloat16* __restrict__ hi,
                             __nv_bfloat16* __restrict__ lo, int n4) {
    int i = blockIdx.x * blockDim.x + threadIdx.x;
    if (i >= n4) return;
    float4 v = ((const float4*)in)[i];
    float vv[4] = {v.x, v.y, v.z, v.w};
    __nv_bfloat16 h[4], l[4];
    #pragma unroll
    for (int j = 0; j < 4; j++) {
        h[j] = __float2bfloat16(vv[j]);
        l[j] = __float2bfloat16(vv[j] - __bfloat162float(h[j]));
    }
    ((ushort4*)hi)[i] = make_ushort4(*(uint16_t*)&h[0], *(uint16_t*)&h[1], *(uint16_t*)&h[2], *(uint16_t*)&h[3]);
    ((ushort4*)lo)[i] = make_ushort4(*(uint16_t*)&l[0], *(uint16_t*)&l[1], *(uint16_t*)&l[2], *(uint16_t*)&l[3]);
}
__global__ void wsplit_kernel(const float* __restrict__ W, __nv_bfloat16* __restrict__ thi,
                              __nv_bfloat16* __restrict__ tlo, int K, int Nc) {
    int i = blockIdx.x * blockDim.x + threadIdx.x;
    if (i >= K * Nc) return;
    int k = i / Nc, c = i - k * Nc;
    float v = W[i];
    __nv_bfloat16 h = __float2bfloat16(v);
    thi[c * K + k] = h;
    tlo[c * K + k] = __float2bfloat16(v - __bfloat162float(h));
}
__global__ void fuse_mlp_kernel(const float* __restrict__ Wf1, const float* __restrict__ bf1,
                                const float* __restrict__ Wf2, const float* __restrict__ bf2) {
    int i = blockIdx.x * blockDim.x + threadIdx.x;
    if (i < HC * OUTC) {
        int r = i >> 5, c = i & 31;
        float s = 0.f;
        #pragma unroll 8
        for (int j = 0; j < 64; j++) s += Wf1[r * 64 + j] * Wf2[j * OUTC + c];
        __nv_bfloat16 h = __float2bfloat16(s);
        g_wfthi[c * HC + r] = h;
        g_wftlo[c * HC + r] = __float2bfloat16(s - __bfloat162float(h));
    } else if (i < HC * OUTC + OUTC) {
        int c = i - HC * OUTC;
        float s = bf2[c];
        for (int j = 0; j < 64; j++) s += bf1[j] * Wf2[j * OUTC + c];
        g_bf[c] = s;
    }
}

// ---------------- bf16-split tensor-core GEMM, double-buffered cp.async ----------------
#define BM 128
#define BN 64
#define BK 32
#define RS 40
#define SA_HI 0
#define SA_LO 5120
#define SB_HI 10240
#define SB_LO 12800
#define STAGE 15360
#define SMEMB (2 * STAGE * 2)   // 61440 bytes

template <bool FUSE, bool OUT16>
__global__ void __launch_bounds__(256, 3) gemm_bf16(const __nv_bfloat16* __restrict__ Ahi,
                                                    const __nv_bfloat16* __restrict__ Alo,
                                                    const __nv_bfloat16* __restrict__ Bthi,
                                                    const __nv_bfloat16* __restrict__ Btlo,
                                                    const float* __restrict__ bias,
                                                    void* __restrict__ Cv,
                                                    const float* __restrict__ asrc,
                                                    const float* __restrict__ adst,
                                                    int M, int K, int Nc) {
    extern __shared__ __nv_bfloat16 smem[];
    uint32_t sbase = smem_u32(smem);

    int tid = threadIdx.x;
    int lane = tid & 31, warp = tid >> 5;
    int wm = warp & 3, wn = warp >> 2;
    int row0 = blockIdx.y * BM, col0 = blockIdx.x * BN;

    int aRow = ((lane & 8) ? 8 : 0) + (lane & 7);
    int aChk = (lane & 16) ? 1 : 0;

    float acc[2][4][4];
    #pragma unroll
    for (int i = 0; i < 2; i++)
        #pragma unroll
        for (int j = 0; j < 4; j++)
            #pragma unroll
            for (int k = 0; k < 4; k++) acc[i][j][k] = 0.f;

    const int ntiles = K / BK;

    auto load_stage = [&](int t, int st) {
        uint32_t sb = sbase + (uint32_t)(st * STAGE * 2);
        int kt = t * BK;
        #pragma unroll
        for (int j = 0; j < 2; j++) {
            int idx = tid + j * 256;
            int r = idx >> 2, ch = idx & 3;
            int gr = row0 + r;
            bool p = gr < M;
            size_t go = (size_t)gr * K + kt + ch * 8;
            uint32_t dof = (uint32_t)((r * RS + ch * 8) * 2);
            cpasync16(sb + SA_HI * 2 + dof, Ahi + go, p);
            cpasync16(sb + SA_LO * 2 + dof, Alo + go, p);
        }
        {
            int r = tid >> 2, ch = tid & 3;
            int gc = col0 + r;
            bool p = gc < Nc;
            size_t go = (size_t)gc * K + kt + ch * 8;
            uint32_t dof = (uint32_t)((r * RS + ch * 8) * 2);
            cpasync16(sb + SB_HI * 2 + dof, Bthi + go, p);
            cpasync16(sb + SB_LO * 2 + dof, Btlo + go, p);
        }
        cp_commit();
    };

    load_stage(0, 0);

    for (int t = 0; t < ntiles; t++) {
        if (t + 1 < ntiles) { load_stage(t + 1, (t + 1) & 1); cp_wait<1>(); }
        else cp_wait<0>();
        __syncthreads();

        uint32_t sb = sbase + (uint32_t)((t & 1) * STAGE * 2);
        uint32_t uAhi = sb + SA_HI * 2, uAlo = sb + SA_LO * 2;
        uint32_t uBhi = sb + SB_HI * 2, uBlo = sb + SB_LO * 2;

        #pragma unroll
        for (int s = 0; s < 2; s++) {
            int kc = 2 * s;
            uint32_t ah0[4], ah1[4], al0[4], al1[4];
            {
                uint32_t base = (uint32_t)(((wm * 32 + aRow) * RS + (kc + aChk) * 8) * 2);
                ldsm4(ah0[0], ah0[1], ah0[2], ah0[3], uAhi + base);
                ldsm4(al0[0], al0[1], al0[2], al0[3], uAlo + base);
                uint32_t base1 = base + (uint32_t)(16 * RS * 2);
                ldsm4(ah1[0], ah1[1], ah1[2], ah1[3], uAhi + base1);
                ldsm4(al1[0], al1[1], al1[2], al1[3], uAlo + base1);
            }
            uint32_t bh_a[4], bh_b[4], bl_a[4], bl_b[4];
            {
                uint32_t base = (uint32_t)(((wn * 32 + lane) * RS + kc * 8) * 2);
                ldsm4(bh_a[0], bh_a[1], bh_a[2], bh_a[3], uBhi + base);
                ldsm4(bl_a[0], bl_a[1], bl_a[2], bl_a[3], uBlo + base);
                uint32_t base1 = base + 16;
                ldsm4(bh_b[0], bh_b[1], bh_b[2], bh_b[3], uBhi + base1);
                ldsm4(bl_b[0], bl_b[1], bl_b[2], bl_b[3], uBlo + base1);
            }
            #pragma unroll
            for (int ni = 0; ni < 4; ni++) {
                uint32_t bh[2] = {bh_a[ni], bh_b[ni]};
                uint32_t bl[2] = {bl_a[ni], bl_b[ni]};
                mma_bf16(acc[0][ni], ah0, bh);
                mma_bf16(acc[0][ni], ah0, bl);
                mma_bf16(acc[0][ni], al0, bh);
                mma_bf16(acc[1][ni], ah1, bh);
                mma_bf16(acc[1][ni], ah1, bl);
                mma_bf16(acc[1][ni], al1, bh);
            }
        }
        __syncthreads();
    }

    // ---- epilogue: C store ----
    int lq = lane >> 2, lr = lane & 3;
    #pragma unroll
    for (int mi = 0; mi < 2; mi++) {
        int r0 = row0 + wm * 32 + mi * 16 + lq;
        #pragma unroll
        for (int ni = 0; ni < 4; ni++) {
            int c = col0 + wn * 32 + ni * 8 + lr * 2;
            if (c < Nc) {
                if (OUT16) {
                    __half* C = (__half*)Cv;
                    if (r0 < M)
                        *(__half2*)(C + (size_t)r0 * Nc + c) =
                            __floats2half2_rn(acc[mi][ni][0], acc[mi][ni][1]);
                    if (r0 + 8 < M)
                        *(__half2*)(C + (size_t)(r0 + 8) * Nc + c) =
                            __floats2half2_rn(acc[mi][ni][2], acc[mi][ni][3]);
                } else {
                    float* C = (float*)Cv;
                    float b0 = bias ? bias[c] : 0.f;
                    float b1 = bias ? bias[c + 1] : 0.f;
                    if (r0 < M)
                        *(float2*)(C + (size_t)r0 * Nc + c) =
                            make_float2(acc[mi][ni][0] + b0, acc[mi][ni][1] + b1);
                    if (r0 + 8 < M)
                        *(float2*)(C + (size_t)(r0 + 8) * Nc + c) =
                            make_float2(acc[mi][ni][2] + b0, acc[mi][ni][3] + b1);
                }
            }
        }
    }

    // ---- fused alpha projections (head = col tile), atomic-free ----
    if (FUSE) {
        float* sred = (float*)smem;
        int head = col0 >> 6;
        #pragma unroll
        for (int mi = 0; mi < 2; mi++) {
            float s0 = 0.f, s1 = 0.f, d0 = 0.f, d1 = 0.f;
            #pragma unroll
            for (int ni = 0; ni < 4; ni++) {
                int c = col0 + wn * 32 + ni * 8 + lr * 2;
                float ws0 = asrc[c], ws1 = asrc[c + 1];
                float wd0 = adst[c], wd1 = adst[c + 1];
                s0 += acc[mi][ni][0] * ws0 + acc[mi][ni][1] * ws1;
                s1 += acc[mi][ni][2] * ws0 + acc[mi][ni][3] * ws1;
                d0 += acc[mi][ni][0] * wd0 + acc[mi][ni][1] * wd1;
                d1 += acc[mi][ni][2] * wd0 + acc[mi][ni][3] * wd1;
            }
            #pragma unroll
            for (int o = 1; o <= 2; o <<= 1) {
                s0 += __shfl_xor_sync(0xffffffffu, s0, o);
                s1 += __shfl_xor_sync(0xffffffffu, s1, o);
                d0 += __shfl_xor_sync(0xffffffffu, d0, o);
                d1 += __shfl_xor_sync(0xffffffffu, d1, o);
            }
            if (lr == 0) {
                int rl0 = wm * 32 + mi * 16 + lq;
                sred[rl0 * 2 + wn] = s0;
                sred[(rl0 + 8) * 2 + wn] = s1;
                sred[256 + rl0 * 2 + wn] = d0;
                sred[256 + (rl0 + 8) * 2 + wn] = d1;
            }
        }
        __syncthreads();
        if (tid < 128) {
            int gr = row0 + tid;
            if (gr < M) {
                g_as[gr * 3 + head] = sred[tid * 2] + sred[tid * 2 + 1];
                g_ad[gr * 3 + head] = sred[256 + tid * 2] + sred[256 + tid * 2 + 1];
            }
        }
    }
}

// ---------------- GAT aggregation: warp/node, per-edge exp computed ONCE ----------------
__global__ void agg_kernel(const __half* __restrict__ h, const float* __restrict__ bias,
                           __nv_bfloat16* __restrict__ ohi, __nv_bfloat16* __restrict__ olo) {
    int gw = (blockIdx.x * blockDim.x + threadIdx.x) >> 5;
    int lane = threadIdx.x & 31;
    if (gw >= NN) return;
    int beg = g_rowptr[gw], end = g_rowptr[gw + 1];
    float ad0 = g_ad[gw * 3 + 0], ad1 = g_ad[gw * 3 + 1], ad2 = g_ad[gw * 3 + 2];

    float d0 = 0.f, d1 = 0.f, d2 = 0.f;
    for (int i = beg + lane; i < end; i += 32) {
        int s = g_srcs[i];
        float e0 = __expf(lrelu(g_as[s * 3 + 0] + ad0));
        float e1 = __expf(lrelu(g_as[s * 3 + 1] + ad1));
        float e2 = __expf(lrelu(g_as[s * 3 + 2] + ad2));
        g_ew[i] = make_float4(e0, e1, e2, 0.f);
        d0 += e0; d1 += e1; d2 += e2;
    }
    d0 = wsum(d0); d1 = wsum(d1); d2 = wsum(d2);
    float i0 = 1.f / (d0 + 1e-16f), i1 = 1.f / (d1 + 1e-16f), i2 = 1.f / (d2 + 1e-16f);

    float2 a0 = make_float2(0.f, 0.f), a1 = a0, a2 = a0;
    #pragma unroll 4
    for (int i = beg; i < end; i++) {
        int s = g_srcs[i];
        float4 w = g_ew[i];
        const __half2* hs = (const __half2*)(h + (size_t)s * HC);
        float2 f0 = __half22float2(hs[lane]);
        float2 f1 = __half22float2(hs[32 + lane]);
        float2 f2 = __half22float2(hs[64 + lane]);
        a0.x += f0.x * w.x; a0.y += f0.y * w.x;
        a1.x += f1.x * w.y; a1.y += f1.y * w.y;
        a2.x += f2.x * w.z; a2.y += f2.y * w.z;
    }
    a0.x *= i0; a0.y *= i0;
    a1.x *= i1; a1.y *= i1;
    a2.x *= i2; a2.y *= i2;

    float2 av[3] = {a0, a1, a2};
    #pragma unroll
    for (int q = 0; q < 3; q++) {
        int c = q * 64 + 2 * lane;
        float v0 = elu_f(av[q].x + bias[c]);
        float v1 = elu_f(av[q].y + bias[c + 1]);
        __nv_bfloat16 h0 = __float2bfloat16(v0), h1 = __float2bfloat16(v1);
        __nv_bfloat16 l0 = __float2bfloat16(v0 - __bfloat162float(h0));
        __nv_bfloat16 l1 = __float2bfloat16(v1 - __bfloat162float(h1));
        size_t idx = (size_t)gw * HC + c;
        __nv_bfloat162 hp; hp.x = h0; hp.y = h1;
        __nv_bfloat162 lp; lp.x = l0; lp.y = l1;
        *(__nv_bfloat162*)(ohi + idx) = hp;
        *(__nv_bfloat162*)(olo + idx) = lp;
    }
}

// ---------------- side-stream resources (host objects, created at load) ----------------
static cudaStream_t g_s2;
static cudaEvent_t  g_evFork, g_evJoin;
static struct SideInit {
    SideInit() {
        cudaStreamCreateWithFlags(&g_s2, cudaStreamNonBlocking);
        cudaEventCreateWithFlags(&g_evFork, cudaEventDisableTiming);
        cudaEventCreateWithFlags(&g_evJoin, cudaEventDisableTiming);
    }
} g_sideInit;

// ---------------- launch ----------------
extern "C" void kernel_launch(void* const* d_in, const int* in_sizes, int n_in,
                              void* d_out, int out_size) {
    const float* x     = (const float*)d_in[0];
    const int*   ei    = (const int*)  d_in[1];
    const float* W1    = (const float*)d_in[2];
    const float* asrc1 = (const float*)d_in[3];
    const float* adst1 = (const float*)d_in[4];
    const float* b1    = (const float*)d_in[5];
    const float* W2    = (const float*)d_in[6];
    const float* asrc2 = (const float*)d_in[7];
    const float* adst2 = (const float*)d_in[8];
    const float* b2    = (const float*)d_in[9];
    const float* Wf1   = (const float*)d_in[10];
    const float* bf1   = (const float*)d_in[11];
    const float* Wf2   = (const float*)d_in[12];
    const float* bf2   = (const float*)d_in[13];
    float* out = (float*)d_out;

    float *bf;
    __half* h;
    __nv_bfloat16 *xhi, *xlo, *hxhi, *hxlo, *w1thi, *w1tlo, *w2thi, *w2tlo, *wfthi, *wftlo;
    cudaGetSymbolAddress((void**)&h,     g_h);
    cudaGetSymbolAddress((void**)&bf,    g_bf);
    cudaGetSymbolAddress((void**)&xhi,   g_xhi);
    cudaGetSymbolAddress((void**)&xlo,   g_xlo);
    cudaGetSymbolAddress((void**)&hxhi,  g_hxhi);
    cudaGetSymbolAddress((void**)&hxlo,  g_hxlo);
    cudaGetSymbolAddress((void**)&w1thi, g_w1thi);
    cudaGetSymbolAddress((void**)&w1tlo, g_w1tlo);
    cudaGetSymbolAddress((void**)&w2thi, g_w2thi);
    cudaGetSymbolAddress((void**)&w2tlo, g_w2tlo);
    cudaGetSymbolAddress((void**)&wfthi, g_wfthi);
    cudaGetSymbolAddress((void**)&wftlo, g_wftlo);

    const int* srcp = ei;
    const int* dstp = ei + EE;

    cudaFuncSetAttribute(gemm_bf16<true, true>,   cudaFuncAttributeMaxDynamicSharedMemorySize, SMEMB);
    cudaFuncSetAttribute(gemm_bf16<false, false>, cudaFuncAttributeMaxDynamicSharedMemorySize, SMEMB);

    int warpBlocks = (NN * 32 + 255) / 256;
    int gy = (NN + BM - 1) / BM;

    // ---- fork: CSR build + MLP fuse on side stream (independent of GEMM path) ----
    cudaEventRecord(g_evFork, 0);
    cudaStreamWaitEvent(g_s2, g_evFork, 0);
    zero_kernel<<<(NN + 255) / 256, 256, 0, g_s2>>>();
    count_kernel<<<(ET + 255) / 256, 256, 0, g_s2>>>(dstp);
    scan_kernel<<<1, 1024, 0, g_s2>>>();
    bucket_kernel<<<(ET + 255) / 256, 256, 0, g_s2>>>(srcp, dstp);
    fuse_mlp_kernel<<<(HC * OUTC + OUTC + 255) / 256, 256, 0, g_s2>>>(Wf1, bf1, Wf2, bf2);
    cudaEventRecord(g_evJoin, g_s2);

    // ---- main stream: operand prep + layer-1 GEMM (+fused alpha) ----
    split_kernel<<<(NN * INC / 4 + 255) / 256, 256>>>(x, xhi, xlo, NN * INC / 4);
    wsplit_kernel<<<(INC * HC + 255) / 256, 256>>>(W1, w1thi, w1tlo, INC, HC);
    wsplit_kernel<<<(HC * HC + 255) / 256, 256>>>(W2, w2thi, w2tlo, HC, HC);
    gemm_bf16<true, true><<<dim3(HC / BN, gy), 256, SMEMB>>>(xhi, xlo, w1thi, w1tlo, nullptr, h,
                                                             asrc1, adst1, NN, INC, HC);

    // ---- join: agg needs CSR ----
    cudaStreamWaitEvent(0, g_evJoin, 0);
    agg_kernel<<<warpBlocks, 256>>>(h, b1, hxhi, hxlo);

    // layer 2
    gemm_bf16<true, true><<<dim3(HC / BN, gy), 256, SMEMB>>>(hxhi, hxlo, w2thi, w2tlo, nullptr, h,
                                                             asrc2, adst2, NN, HC, HC);
    agg_kernel<<<warpBlocks, 256>>>(h, b2, hxhi, hxlo);

    // fused MLP head
    gemm_bf16<false, false><<<dim3(1, gy), 256, SMEMB>>>(hxhi, hxlo, wfthi, wftlo, bf, out,
                                                         nullptr, nullptr, NN, HC, OUTC);
}

// round 9
// speedup vs baseline: 3.1622x; 1.1057x over previous
#include <cuda_runtime.h>
#include <cuda_fp16.h>
#include <math.h>
#include <stdint.h>

#define NN   50000
#define EE   800000
#define ET   (EE + NN)
#define INC  128
#define HC   192
#define OUTC 32

// ---------------- scratch ----------------
__device__ __half g_h[NN * HC];                       // gemm output -> agg input (fp16)
__device__ __half g_hx16[NN * HC];                    // agg output -> gemm input (fp16)
__device__ __half g_x16[NN * INC];                    // x quantized fp16
__device__ float4 g_ew[ET];                           // per-edge exp weights
__device__ __half g_w1thi[HC * INC], g_w1tlo[HC * INC];
__device__ __half g_w2thi[HC * HC],  g_w2tlo[HC * HC];
__device__ __half g_wfthi[OUTC * HC], g_wftlo[OUTC * HC];
__device__ float g_bf[OUTC];
__device__ float g_as[NN * 3];
__device__ float g_ad[NN * 3];
__device__ int   g_deg[NN];
__device__ int   g_ctr[NN];
__device__ int   g_rowptr[NN + 1];
__device__ int   g_srcs[ET];

// ---------------- helpers ----------------
__device__ __forceinline__ float lrelu(float v) { return v > 0.f ? v : 0.2f * v; }
__device__ __forceinline__ float elu_f(float v) { return v > 0.f ? v : expm1f(v); }
__device__ __forceinline__ float wsum(float v) {
    #pragma unroll
    for (int o = 16; o > 0; o >>= 1) v += __shfl_xor_sync(0xffffffffu, v, o);
    return v;
}
__device__ __forceinline__ uint32_t smem_u32(const void* p) {
    uint32_t a;
    asm("{ .reg .u64 t; cvta.to.shared.u64 t, %1; cvt.u32.u64 %0, t; }" : "=r"(a) : "l"(p));
    return a;
}
__device__ __forceinline__ void ldsm4(uint32_t& r0, uint32_t& r1, uint32_t& r2, uint32_t& r3, uint32_t a) {
    asm volatile("ldmatrix.sync.aligned.m8n8.x4.shared.b16 {%0,%1,%2,%3}, [%4];"
                 : "=r"(r0), "=r"(r1), "=r"(r2), "=r"(r3) : "r"(a));
}
__device__ __forceinline__ void mma_f16(float* c, const uint32_t* a, const uint32_t* b) {
    asm volatile(
        "mma.sync.aligned.m16n8k16.row.col.f32.f16.f16.f32 "
        "{%0,%1,%2,%3}, {%4,%5,%6,%7}, {%8,%9}, {%0,%1,%2,%3};"
        : "+f"(c[0]), "+f"(c[1]), "+f"(c[2]), "+f"(c[3])
        : "r"(a[0]), "r"(a[1]), "r"(a[2]), "r"(a[3]), "r"(b[0]), "r"(b[1]));
}
__device__ __forceinline__ void cpasync16(uint32_t dst, const void* src, bool pred) {
    int sz = pred ? 16 : 0;
    asm volatile("cp.async.cg.shared.global [%0], [%1], 16, %2;"
                 :: "r"(dst), "l"(src), "r"(sz) : "memory");
}
__device__ __forceinline__ void cp_commit() { asm volatile("cp.async.commit_group;" ::: "memory"); }
template <int N>
__device__ __forceinline__ void cp_wait() { asm volatile("cp.async.wait_group %0;" :: "n"(N) : "memory"); }

// ---------------- CSR build ----------------
__global__ void zero_kernel() {
    int i = blockIdx.x * blockDim.x + threadIdx.x;
    if (i < NN) { g_deg[i] = 0; g_ctr[i] = 0; }
}
__global__ void count_kernel(const int* __restrict__ dst) {
    int i = blockIdx.x * blockDim.x + threadIdx.x;
    if (i >= ET) return;
    int d = (i < EE) ? dst[i] : (i - EE);
    atomicAdd(&g_deg[d], 1);
}
__global__ void scan_kernel() {
    __shared__ int part[1024];
    const int per = (NN + 1023) / 1024;
    int t = threadIdx.x;
    int start = t * per, end = min(start + per, NN);
    int s = 0;
    for (int i = start; i < end; i++) s += g_deg[i];
    part[t] = s;
    __syncthreads();
    for (int off = 1; off < 1024; off <<= 1) {
        int v = (t >= off) ? part[t - off] : 0;
        __syncthreads();
        part[t] += v;
        __syncthreads();
    }
    int run = part[t] - s;
    for (int i = start; i < end; i++) { g_rowptr[i] = run; run += g_deg[i]; }
    if (t == 1023) g_rowptr[NN] = part[1023];
}
__global__ void bucket_kernel(const int* __restrict__ src, const int* __restrict__ dst) {
    int i = blockIdx.x * blockDim.x + threadIdx.x;
    if (i >= ET) return;
    int s, d;
    if (i < EE) { s = src[i]; d = dst[i]; } else { s = i - EE; d = s; }
    int pos = atomicAdd(&g_ctr[d], 1);
    g_srcs[g_rowptr[d] + pos] = s;
}

// ---------------- operand prep ----------------
__global__ void x16_kernel(const float* __restrict__ in, __half* __restrict__ o16, int n4) {
    int i = blockIdx.x * blockDim.x + threadIdx.x;
    if (i >= n4) return;
    float4 v = ((const float4*)in)[i];
    __half2 a = __floats2half2_rn(v.x, v.y);
    __half2 b = __floats2half2_rn(v.z, v.w);
    ((uint2*)o16)[i] = make_uint2(*(uint32_t*)&a, *(uint32_t*)&b);
}
// W[K][Nc] -> transposed fp16 hi/lo tables [Nc][K]
__global__ void wsplit_kernel(const float* __restrict__ W, __half* __restrict__ thi,
                              __half* __restrict__ tlo, int K, int Nc) {
    int i = blockIdx.x * blockDim.x + threadIdx.x;
    if (i >= K * Nc) return;
    int k = i / Nc, c = i - k * Nc;
    float v = W[i];
    __half h = __float2half_rn(v);
    thi[c * K + k] = h;
    tlo[c * K + k] = __float2half_rn(v - __half2float(h));
}
__global__ void fuse_mlp_kernel(const float* __restrict__ Wf1, const float* __restrict__ bf1,
                                const float* __restrict__ Wf2, const float* __restrict__ bf2) {
    int i = blockIdx.x * blockDim.x + threadIdx.x;
    if (i < HC * OUTC) {
        int r = i >> 5, c = i & 31;
        float s = 0.f;
        #pragma unroll 8
        for (int j = 0; j < 64; j++) s += Wf1[r * 64 + j] * Wf2[j * OUTC + c];
        __half h = __float2half_rn(s);
        g_wfthi[c * HC + r] = h;
        g_wftlo[c * HC + r] = __float2half_rn(s - __half2float(h));
    } else if (i < HC * OUTC + OUTC) {
        int c = i - HC * OUTC;
        float s = bf2[c];
        for (int j = 0; j < 64; j++) s += bf1[j] * Wf2[j * OUTC + c];
        g_bf[c] = s;
    }
}

// ---------------- fp16 A x fp16-split B tensor-core GEMM, double-buffered ----------------
// C[M,Nc] = A[M,K] @ Bt[Nc,K]^T. A plain fp16, B split hi+lo: 2 MMAs per fragment.
#define BM 128
#define BN 64
#define BK 32
#define RS 40
// stage layout in half elems
#define SA_OFF 0
#define SB_HI  5120
#define SB_LO  7680
#define STAGE  10240
#define SMEMB (2 * STAGE * 2)   // 40960 bytes

template <bool FUSE, bool OUT16>
__global__ void __launch_bounds__(256, 3) gemm_f16(const __half* __restrict__ A,
                                                   const __half* __restrict__ Bthi,
                                                   const __half* __restrict__ Btlo,
                                                   const float* __restrict__ bias,
                                                   void* __restrict__ Cv,
                                                   const float* __restrict__ asrc,
                                                   const float* __restrict__ adst,
                                                   int M, int K, int Nc) {
    extern __shared__ __half smem[];
    uint32_t sbase = smem_u32(smem);

    int tid = threadIdx.x;
    int lane = tid & 31, warp = tid >> 5;
    int wm = warp & 3, wn = warp >> 2;
    int row0 = blockIdx.y * BM, col0 = blockIdx.x * BN;

    int aRow = ((lane & 8) ? 8 : 0) + (lane & 7);
    int aChk = (lane & 16) ? 1 : 0;

    float acc[2][4][4];
    #pragma unroll
    for (int i = 0; i < 2; i++)
        #pragma unroll
        for (int j = 0; j < 4; j++)
            #pragma unroll
            for (int k = 0; k < 4; k++) acc[i][j][k] = 0.f;

    const int ntiles = K / BK;

    auto load_stage = [&](int t, int st) {
        uint32_t sb = sbase + (uint32_t)(st * STAGE * 2);
        int kt = t * BK;
        // A: 128 rows x 4 chunks of 16B (fp16), 512 ops = 2/thread
        #pragma unroll
        for (int j = 0; j < 2; j++) {
            int idx = tid + j * 256;
            int r = idx >> 2, ch = idx & 3;
            int gr = row0 + r;
            bool p = gr < M;
            size_t go = (size_t)gr * K + kt + ch * 8;
            uint32_t dof = (uint32_t)((r * RS + ch * 8) * 2);
            cpasync16(sb + SA_OFF * 2 + dof, A + go, p);
        }
        // B: 64 rows x 4 chunks, hi+lo
        {
            int r = tid >> 2, ch = tid & 3;
            int gc = col0 + r;
            bool p = gc < Nc;
            size_t go = (size_t)gc * K + kt + ch * 8;
            uint32_t dof = (uint32_t)((r * RS + ch * 8) * 2);
            cpasync16(sb + SB_HI * 2 + dof, Bthi + go, p);
            cpasync16(sb + SB_LO * 2 + dof, Btlo + go, p);
        }
        cp_commit();
    };

    load_stage(0, 0);

    for (int t = 0; t < ntiles; t++) {
        if (t + 1 < ntiles) { load_stage(t + 1, (t + 1) & 1); cp_wait<1>(); }
        else cp_wait<0>();
        __syncthreads();

        uint32_t sb = sbase + (uint32_t)((t & 1) * STAGE * 2);
        uint32_t uA = sb + SA_OFF * 2;
        uint32_t uBhi = sb + SB_HI * 2, uBlo = sb + SB_LO * 2;

        #pragma unroll
        for (int s = 0; s < 2; s++) {
            int kc = 2 * s;
            uint32_t a0[4], a1[4];
            {
                uint32_t base = (uint32_t)(((wm * 32 + aRow) * RS + (kc + aChk) * 8) * 2);
                ldsm4(a0[0], a0[1], a0[2], a0[3], uA + base);
                uint32_t base1 = base + (uint32_t)(16 * RS * 2);
                ldsm4(a1[0], a1[1], a1[2], a1[3], uA + base1);
            }
            uint32_t bh_a[4], bh_b[4], bl_a[4], bl_b[4];
            {
                uint32_t base = (uint32_t)(((wn * 32 + lane) * RS + kc * 8) * 2);
                ldsm4(bh_a[0], bh_a[1], bh_a[2], bh_a[3], uBhi + base);
                ldsm4(bl_a[0], bl_a[1], bl_a[2], bl_a[3], uBlo + base);
                uint32_t base1 = base + 16;
                ldsm4(bh_b[0], bh_b[1], bh_b[2], bh_b[3], uBhi + base1);
                ldsm4(bl_b[0], bl_b[1], bl_b[2], bl_b[3], uBlo + base1);
            }
            #pragma unroll
            for (int ni = 0; ni < 4; ni++) {
                uint32_t bh[2] = {bh_a[ni], bh_b[ni]};
                uint32_t bl[2] = {bl_a[ni], bl_b[ni]};
                mma_f16(acc[0][ni], a0, bh);
                mma_f16(acc[0][ni], a0, bl);
                mma_f16(acc[1][ni], a1, bh);
                mma_f16(acc[1][ni], a1, bl);
            }
        }
        __syncthreads();
    }

    // ---- epilogue: C store ----
    int lq = lane >> 2, lr = lane & 3;
    #pragma unroll
    for (int mi = 0; mi < 2; mi++) {
        int r0 = row0 + wm * 32 + mi * 16 + lq;
        #pragma unroll
        for (int ni = 0; ni < 4; ni++) {
            int c = col0 + wn * 32 + ni * 8 + lr * 2;
            if (c < Nc) {
                if (OUT16) {
                    __half* C = (__half*)Cv;
                    if (r0 < M)
                        *(__half2*)(C + (size_t)r0 * Nc + c) =
                            __floats2half2_rn(acc[mi][ni][0], acc[mi][ni][1]);
                    if (r0 + 8 < M)
                        *(__half2*)(C + (size_t)(r0 + 8) * Nc + c) =
                            __floats2half2_rn(acc[mi][ni][2], acc[mi][ni][3]);
                } else {
                    float* C = (float*)Cv;
                    float b0 = bias ? bias[c] : 0.f;
                    float b1 = bias ? bias[c + 1] : 0.f;
                    if (r0 < M)
                        *(float2*)(C + (size_t)r0 * Nc + c) =
                            make_float2(acc[mi][ni][0] + b0, acc[mi][ni][1] + b1);
                    if (r0 + 8 < M)
                        *(float2*)(C + (size_t)(r0 + 8) * Nc + c) =
                            make_float2(acc[mi][ni][2] + b0, acc[mi][ni][3] + b1);
                }
            }
        }
    }

    // ---- fused alpha projections (head = col tile), atomic-free ----
    if (FUSE) {
        float* sred = (float*)smem;
        int head = col0 >> 6;
        #pragma unroll
        for (int mi = 0; mi < 2; mi++) {
            float s0 = 0.f, s1 = 0.f, d0 = 0.f, d1 = 0.f;
            #pragma unroll
            for (int ni = 0; ni < 4; ni++) {
                int c = col0 + wn * 32 + ni * 8 + lr * 2;
                float ws0 = asrc[c], ws1 = asrc[c + 1];
                float wd0 = adst[c], wd1 = adst[c + 1];
                s0 += acc[mi][ni][0] * ws0 + acc[mi][ni][1] * ws1;
                s1 += acc[mi][ni][2] * ws0 + acc[mi][ni][3] * ws1;
                d0 += acc[mi][ni][0] * wd0 + acc[mi][ni][1] * wd1;
                d1 += acc[mi][ni][2] * wd0 + acc[mi][ni][3] * wd1;
            }
            #pragma unroll
            for (int o = 1; o <= 2; o <<= 1) {
                s0 += __shfl_xor_sync(0xffffffffu, s0, o);
                s1 += __shfl_xor_sync(0xffffffffu, s1, o);
                d0 += __shfl_xor_sync(0xffffffffu, d0, o);
                d1 += __shfl_xor_sync(0xffffffffu, d1, o);
            }
            if (lr == 0) {
                int rl0 = wm * 32 + mi * 16 + lq;
                sred[rl0 * 2 + wn] = s0;
                sred[(rl0 + 8) * 2 + wn] = s1;
                sred[256 + rl0 * 2 + wn] = d0;
                sred[256 + (rl0 + 8) * 2 + wn] = d1;
            }
        }
        __syncthreads();
        if (tid < 128) {
            int gr = row0 + tid;
            if (gr < M) {
                g_as[gr * 3 + head] = sred[tid * 2] + sred[tid * 2 + 1];
                g_ad[gr * 3 + head] = sred[256 + tid * 2] + sred[256 + tid * 2 + 1];
            }
        }
    }
}

// ---------------- GAT aggregation: warp/node, exp once per edge, fp16 I/O ----------------
__global__ void agg_kernel(const __half* __restrict__ h, const float* __restrict__ bias,
                           __half* __restrict__ o16) {
    int gw = (blockIdx.x * blockDim.x + threadIdx.x) >> 5;
    int lane = threadIdx.x & 31;
    if (gw >= NN) return;
    int beg = g_rowptr[gw], end = g_rowptr[gw + 1];
    float ad0 = g_ad[gw * 3 + 0], ad1 = g_ad[gw * 3 + 1], ad2 = g_ad[gw * 3 + 2];

    float d0 = 0.f, d1 = 0.f, d2 = 0.f;
    for (int i = beg + lane; i < end; i += 32) {
        int s = g_srcs[i];
        float e0 = __expf(lrelu(g_as[s * 3 + 0] + ad0));
        float e1 = __expf(lrelu(g_as[s * 3 + 1] + ad1));
        float e2 = __expf(lrelu(g_as[s * 3 + 2] + ad2));
        g_ew[i] = make_float4(e0, e1, e2, 0.f);
        d0 += e0; d1 += e1; d2 += e2;
    }
    d0 = wsum(d0); d1 = wsum(d1); d2 = wsum(d2);
    float i0 = 1.f / (d0 + 1e-16f), i1 = 1.f / (d1 + 1e-16f), i2 = 1.f / (d2 + 1e-16f);

    float2 a0 = make_float2(0.f, 0.f), a1 = a0, a2 = a0;
    #pragma unroll 4
    for (int i = beg; i < end; i++) {
        int s = g_srcs[i];
        float4 w = g_ew[i];
        const __half2* hs = (const __half2*)(h + (size_t)s * HC);
        float2 f0 = __half22float2(hs[lane]);
        float2 f1 = __half22float2(hs[32 + lane]);
        float2 f2 = __half22float2(hs[64 + lane]);
        a0.x += f0.x * w.x; a0.y += f0.y * w.x;
        a1.x += f1.x * w.y; a1.y += f1.y * w.y;
        a2.x += f2.x * w.z; a2.y += f2.y * w.z;
    }
    a0.x *= i0; a0.y *= i0;
    a1.x *= i1; a1.y *= i1;
    a2.x *= i2; a2.y *= i2;

    float2 av[3] = {a0, a1, a2};
    #pragma unroll
    for (int q = 0; q < 3; q++) {
        int c = q * 64 + 2 * lane;
        float v0 = elu_f(av[q].x + bias[c]);
        float v1 = elu_f(av[q].y + bias[c + 1]);
        *(__half2*)(o16 + (size_t)gw * HC + c) = __floats2half2_rn(v0, v1);
    }
}

// ---------------- side-stream resources ----------------
static cudaStream_t g_s2;
static cudaEvent_t  g_evFork, g_evJoin;
static struct SideInit {
    SideInit() {
        cudaStreamCreateWithFlags(&g_s2, cudaStreamNonBlocking);
        cudaEventCreateWithFlags(&g_evFork, cudaEventDisableTiming);
        cudaEventCreateWithFlags(&g_evJoin, cudaEventDisableTiming);
    }
} g_sideInit;

// ---------------- launch ----------------
extern "C" void kernel_launch(void* const* d_in, const int* in_sizes, int n_in,
                              void* d_out, int out_size) {
    const float* x     = (const float*)d_in[0];
    const int*   ei    = (const int*)  d_in[1];
    const float* W1    = (const float*)d_in[2];
    const float* asrc1 = (const float*)d_in[3];
    const float* adst1 = (const float*)d_in[4];
    const float* b1    = (const float*)d_in[5];
    const float* W2    = (const float*)d_in[6];
    const float* asrc2 = (const float*)d_in[7];
    const float* adst2 = (const float*)d_in[8];
    const float* b2    = (const float*)d_in[9];
    const float* Wf1   = (const float*)d_in[10];
    const float* bf1   = (const float*)d_in[11];
    const float* Wf2   = (const float*)d_in[12];
    const float* bf2   = (const float*)d_in[13];
    float* out = (float*)d_out;

    float *bf;
    __half *h, *hx16, *x16, *w1thi, *w1tlo, *w2thi, *w2tlo, *wfthi, *wftlo;
    cudaGetSymbolAddress((void**)&h,     g_h);
    cudaGetSymbolAddress((void**)&hx16,  g_hx16);
    cudaGetSymbolAddress((void**)&x16,   g_x16);
    cudaGetSymbolAddress((void**)&bf,    g_bf);
    cudaGetSymbolAddress((void**)&w1thi, g_w1thi);
    cudaGetSymbolAddress((void**)&w1tlo, g_w1tlo);
    cudaGetSymbolAddress((void**)&w2thi, g_w2thi);
    cudaGetSymbolAddress((void**)&w2tlo, g_w2tlo);
    cudaGetSymbolAddress((void**)&wfthi, g_wfthi);
    cudaGetSymbolAddress((void**)&wftlo, g_wftlo);

    const int* srcp = ei;
    const int* dstp = ei + EE;

    cudaFuncSetAttribute(gemm_f16<true, true>,   cudaFuncAttributeMaxDynamicSharedMemorySize, SMEMB);
    cudaFuncSetAttribute(gemm_f16<false, false>, cudaFuncAttributeMaxDynamicSharedMemorySize, SMEMB);

    int warpBlocks = (NN * 32 + 255) / 256;
    int gy = (NN + BM - 1) / BM;

    // ---- fork: CSR build + MLP fuse on side stream ----
    cudaEventRecord(g_evFork, 0);
    cudaStreamWaitEvent(g_s2, g_evFork, 0);
    zero_kernel<<<(NN + 255) / 256, 256, 0, g_s2>>>();
    count_kernel<<<(ET + 255) / 256, 256, 0, g_s2>>>(dstp);
    scan_kernel<<<1, 1024, 0, g_s2>>>();
    bucket_kernel<<<(ET + 255) / 256, 256, 0, g_s2>>>(srcp, dstp);
    fuse_mlp_kernel<<<(HC * OUTC + OUTC + 255) / 256, 256, 0, g_s2>>>(Wf1, bf1, Wf2, bf2);
    cudaEventRecord(g_evJoin, g_s2);

    // ---- main stream: prep + layer-1 GEMM (+fused alpha) ----
    x16_kernel<<<(NN * INC / 4 + 255) / 256, 256>>>(x, x16, NN * INC / 4);
    wsplit_kernel<<<(INC * HC + 255) / 256, 256>>>(W1, w1thi, w1tlo, INC, HC);
    wsplit_kernel<<<(HC * HC + 255) / 256, 256>>>(W2, w2thi, w2tlo, HC, HC);
    gemm_f16<true, true><<<dim3(HC / BN, gy), 256, SMEMB>>>(x16, w1thi, w1tlo, nullptr, h,
                                                            asrc1, adst1, NN, INC, HC);

    // ---- join: agg needs CSR ----
    cudaStreamWaitEvent(0, g_evJoin, 0);
    agg_kernel<<<warpBlocks, 256>>>(h, b1, hx16);

    // layer 2
    gemm_f16<true, true><<<dim3(HC / BN, gy), 256, SMEMB>>>(hx16, w2thi, w2tlo, nullptr, h,
                                                            asrc2, adst2, NN, HC, HC);
    agg_kernel<<<warpBlocks, 256>>>(h, b2, hx16);

    // fused MLP head
    gemm_f16<false, false><<<dim3(1, gy), 256, SMEMB>>>(hx16, wfthi, wftlo, bf, out,
                                                        nullptr, nullptr, NN, HC, OUTC);
}